// round 5
// baseline (speedup 1.0000x reference)
#include <cuda_runtime.h>
#include <math.h>

#define N_ROWS   8192
#define K_DIM    128
#define TILE     64
#define NTHREADS 256
#define MARGIN   0.1f
#define NBLOCKS  (N_ROWS / TILE)   // 128

// Per-block partial loss sums (no atomics -> deterministic).
__device__ float g_partial[NBLOCKS];
// Normalized int labels (auto-detected int32 vs int64 source layout).
__device__ int   g_lab[N_ROWS];

// ---------------------------------------------------------------------------
// Label normalization. The reference requests int64 labels but JAX without
// x64 silently yields int32 — so the device buffer layout is ambiguous.
// Detection: view buffer as int32 words. If source is int64 (values 0..63),
// every odd word is 0. If source is int32 random labels, the odd words are
// themselves labels (P(all zero) ~ 0). Probe only the first 4096 odd words so
// reads stay in-bounds for BOTH layouts.
// ---------------------------------------------------------------------------
__global__ void fix_labels(const int* __restrict__ lab32)
{
    int local = 0;
    for (int i = threadIdx.x; i < N_ROWS / 2; i += blockDim.x)
        local |= lab32[2 * i + 1];
    int any_odd_nonzero = __syncthreads_or(local);
    if (any_odd_nonzero) {
        // int32 source
        for (int i = threadIdx.x; i < N_ROWS; i += blockDim.x)
            g_lab[i] = lab32[i];
    } else {
        // int64 source (little-endian: value in the even word)
        for (int i = threadIdx.x; i < N_ROWS; i += blockDim.x)
            g_lab[i] = lab32[2 * i];
    }
}

// Swizzled k-major smem layout for a [K][TILE] fp32 tile.
// Element (k, r) lives at word: k*TILE + ((cg ^ ((k>>2)&15))<<2 | ri),
// where cg = r>>2 (float4 group), ri = r&3.
// -> compute-side float4 reads are conflict-free; transpose STS is ~2-way.
__device__ __forceinline__ int sw_group(int k, int cg) {
    return k * TILE + (((cg ^ ((k >> 2) & 15)) << 2));
}

__device__ __forceinline__ void load_tile_transposed(
    float* dst, const float* __restrict__ E, int row_base, int tid)
{
    // 64 rows x 128 cols fp32, 256 threads, float4 global loads (coalesced),
    // scalar transposed+swizzled stores.
    #pragma unroll
    for (int t = 0; t < 8; t++) {
        int idx  = t * NTHREADS + tid;     // 0..2047
        int row  = idx >> 5;               // 0..63
        int colv = idx & 31;               // float4 column 0..31
        float4 v = reinterpret_cast<const float4*>(E)[(size_t)(row_base + row) * (K_DIM / 4) + colv];
        int cg = row >> 2, ri = row & 3;
        int kb = colv * 4;
        dst[sw_group(kb + 0, cg) + ri] = v.x;
        dst[sw_group(kb + 1, cg) + ri] = v.y;
        dst[sw_group(kb + 2, cg) + ri] = v.z;
        dst[sw_group(kb + 3, cg) + ri] = v.w;
    }
}

__global__ __launch_bounds__(NTHREADS)
void npair_main(const float* __restrict__ E)
{
    extern __shared__ float smem[];
    float* As   = smem;                        // K_DIM*TILE = 8192 floats (32 KB)
    float* Bs   = smem + K_DIM * TILE;         // 8192 floats (32 KB)
    int*   sLab = (int*)(smem + 2 * K_DIM * TILE); // 64 ints

    const int tid  = threadIdx.x;
    const int tx   = tid & 15;    // column group 0..15 (4 cols each)
    const int ty   = tid >> 4;    // row group    0..15 (4 rows each)
    const int row0 = blockIdx.x * TILE;

    // Resident A tile for this block (transposed + swizzled).
    load_tile_transposed(As, E, row0, tid);

    // Row labels for this thread's 4 rows (tiny, L2-cached).
    int labr[4];
    #pragma unroll
    for (int i = 0; i < 4; i++) labr[i] = g_lab[row0 + ty * 4 + i];

    float rowsum[4] = {0.f, 0.f, 0.f, 0.f};

    for (int ct = 0; ct < NBLOCKS; ct++) {
        __syncthreads();  // protect Bs/sLab from previous iteration's readers
                          // (also orders the initial As stores before first reads)
        load_tile_transposed(Bs, E, ct * TILE, tid);
        if (tid < TILE) sLab[tid] = g_lab[ct * TILE + tid];
        __syncthreads();

        float acc[4][4];
        #pragma unroll
        for (int i = 0; i < 4; i++)
            #pragma unroll
            for (int j = 0; j < 4; j++) acc[i][j] = 0.f;

        #pragma unroll 8
        for (int k = 0; k < K_DIM; k++) {
            int cgk = (k >> 2) & 15;
            float4 a = *reinterpret_cast<const float4*>(As + k * TILE + (((ty ^ cgk) << 2)));
            float4 b = *reinterpret_cast<const float4*>(Bs + k * TILE + (((tx ^ cgk) << 2)));
            float av[4] = {a.x, a.y, a.z, a.w};
            float bv[4] = {b.x, b.y, b.z, b.w};
            #pragma unroll
            for (int i = 0; i < 4; i++)
                #pragma unroll
                for (int j = 0; j < 4; j++)
                    acc[i][j] += av[i] * bv[j];
        }

        int labc[4];
        #pragma unroll
        for (int j = 0; j < 4; j++) labc[j] = sLab[tx * 4 + j];

        #pragma unroll
        for (int i = 0; i < 4; i++) {
            #pragma unroll
            for (int j = 0; j < 4; j++) {
                float s   = acc[i][j];
                float arg = (labr[i] == labc[j]) ? (MARGIN - s) : (s - MARGIN);
                rowsum[i] += __expf(arg);
            }
        }
    }

    // ---- Block reduction: 16 column-threads per row -> per-row logsum ----
    __syncthreads();
    float* red     = smem;                 // 64 x 16 floats (aliases As; done with it)
    float* lossbuf = smem + TILE * 16;     // 64 floats

    #pragma unroll
    for (int i = 0; i < 4; i++) red[(ty * 4 + i) * 16 + tx] = rowsum[i];
    __syncthreads();

    if (tid < TILE) {
        float s = 0.f;
        #pragma unroll
        for (int t = 0; t < 16; t++) s += red[tid * 16 + t];
        lossbuf[tid] = logf(s);
    }
    __syncthreads();

    if (tid == 0) {
        float s = 0.f;
        #pragma unroll 8
        for (int r = 0; r < TILE; r++) s += lossbuf[r];
        g_partial[blockIdx.x] = s;
    }
}

__global__ void npair_final(float* __restrict__ out)
{
    if (threadIdx.x == 0) {
        float s = 0.f;
        #pragma unroll 8
        for (int b = 0; b < NBLOCKS; b++) s += g_partial[b];
        out[0] = s / (float)N_ROWS;
    }
}

extern "C" void kernel_launch(void* const* d_in, const int* in_sizes, int n_in,
                              void* d_out, int out_size)
{
    const float* E   = (const float*)d_in[0];
    const int*   lab = (const int*)d_in[1];   // raw words; layout auto-detected
    float*       out = (float*)d_out;

    size_t smem_bytes = (size_t)(2 * K_DIM * TILE) * sizeof(float) + TILE * sizeof(int);
    cudaFuncSetAttribute(npair_main, cudaFuncAttributeMaxDynamicSharedMemorySize,
                         (int)smem_bytes);

    fix_labels<<<1, 256>>>(lab);
    npair_main<<<NBLOCKS, NTHREADS, smem_bytes>>>(E);
    npair_final<<<1, 32>>>(out);
}

// round 7
// speedup vs baseline: 7.8091x; 7.8091x over previous
#include <cuda_runtime.h>
#include <cstdint>
#include <math.h>

#define N_ROWS   8192
#define K_DIM    128
#define MT       128              // rows per CTA
#define NT       128              // cols per tile iteration
#define HALF     4096             // cols per CTA (half of matrix)
#define N_ITERS  (HALF / NT)      // 32
#define NTHREADS 256
#define MARGIN   0.1f
#define PADF     132              // floats per padded smem row

// ---- static device scratch ----
__device__ float g_Etf[N_ROWS * K_DIM];   // tf32-rounded embeddings (4 MB)
__device__ float g_rowsum[2][N_ROWS];
__device__ int   g_lab[N_ROWS];

// ---- smem byte offsets ----
#define ROW_BYTES   (PADF * 4)                   // 528
#define TILE_BYTES  (MT * ROW_BYTES)             // 67584
#define SM_A        0
#define SM_B        TILE_BYTES                   // two buffers
#define SM_LAB      (SM_B + 2 * TILE_BYTES)      // int[2][NT]
#define SM_RED      (SM_LAB + 2 * NT * 4)        // float[4][MT]
#define SM_TOTAL    (SM_RED + 4 * MT * 4)        // 205824

__device__ __forceinline__ uint32_t smem_u32(const void* p) {
    uint32_t a;
    asm("{ .reg .u64 t; cvta.to.shared.u64 t, %1; cvt.u32.u64 %0, t; }" : "=r"(a) : "l"(p));
    return a;
}
__device__ __forceinline__ float to_tf32(float x) {
    float r;
    asm("cvt.rna.tf32.f32 %0, %1;" : "=f"(r) : "f"(x));
    return r;
}
__device__ __forceinline__ void cp_async16(uint32_t dst, const void* src) {
    asm volatile("cp.async.cg.shared.global [%0], [%1], 16;" :: "r"(dst), "l"(src) : "memory");
}
#define CP_COMMIT() asm volatile("cp.async.commit_group;" ::: "memory")
#define CP_WAIT1()  asm volatile("cp.async.wait_group 1;" ::: "memory")
#define CP_WAIT0()  asm volatile("cp.async.wait_group 0;" ::: "memory")

__device__ __forceinline__ void mma_tf32(float& c0, float& c1, float& c2, float& c3,
                                         uint32_t a0, uint32_t a1, uint32_t a2, uint32_t a3,
                                         uint32_t b0, uint32_t b1) {
    asm volatile(
        "mma.sync.aligned.m16n8k8.row.col.f32.tf32.tf32.f32 "
        "{%0,%1,%2,%3}, {%4,%5,%6,%7}, {%8,%9}, {%0,%1,%2,%3};"
        : "+f"(c0), "+f"(c1), "+f"(c2), "+f"(c3)
        : "r"(a0), "r"(a1), "r"(a2), "r"(a3), "r"(b0), "r"(b1));
}

// ---------------------------------------------------------------------------
// Prologue 1: normalize labels (int32 vs int64 buffer layout auto-detect).
// ---------------------------------------------------------------------------
__global__ void fix_labels(const int* __restrict__ lab32)
{
    int local = 0;
    for (int i = threadIdx.x; i < N_ROWS / 2; i += blockDim.x)
        local |= lab32[2 * i + 1];
    int any_odd = __syncthreads_or(local);
    if (any_odd) {
        for (int i = threadIdx.x; i < N_ROWS; i += blockDim.x) g_lab[i] = lab32[i];
    } else {
        for (int i = threadIdx.x; i < N_ROWS; i += blockDim.x) g_lab[i] = lab32[2 * i];
    }
}

// ---------------------------------------------------------------------------
// Prologue 2: round embeddings to tf32 once (round-to-nearest, cuBLAS-style).
// ---------------------------------------------------------------------------
__global__ void stage_tf32(const float* __restrict__ E)
{
    int idx = blockIdx.x * blockDim.x + threadIdx.x;
    int stride = gridDim.x * blockDim.x;
    for (int i = idx; i < N_ROWS * K_DIM; i += stride)
        g_Etf[i] = to_tf32(E[i]);
}

// ---------------------------------------------------------------------------
// Main: warp-MMA tf32 GEMM with fused exp/row-sum epilogue.
// Grid 128 = 64 row-blocks x 2 column halves.
// ---------------------------------------------------------------------------
__global__ __launch_bounds__(NTHREADS)
void npair_mma(void)
{
    extern __shared__ char smem[];
    const uint32_t sbase = smem_u32(smem);
    float* As  = (float*)(smem + SM_A);
    int*   labS = (int*)(smem + SM_LAB);      // [2][NT]
    float* red  = (float*)(smem + SM_RED);    // [4][MT]

    const int tid = threadIdx.x;
    const int wid = tid >> 5, lid = tid & 31;
    const int wm = wid >> 2;                  // 0..1  (row 64-block within tile)
    const int wn = wid & 3;                   // 0..3  (col 32-block within tile)
    const int qr = lid >> 2;                  // quad row 0..7
    const int qc = lid & 3;                   // quad col 0..3

    const int rowblk = blockIdx.x >> 1;
    const int half   = blockIdx.x & 1;
    const int row0   = rowblk * MT;
    const int col0   = half * HALF;

    // ---- load resident A tile (128 x 128 f32, padded rows) ----
    #pragma unroll
    for (int t = 0; t < 16; t++) {
        int idx = t * NTHREADS + tid;         // 0..4095
        int row = idx >> 5;
        int c4  = idx & 31;
        float4 v = reinterpret_cast<const float4*>(g_Etf)[(size_t)(row0 + row) * 32 + c4];
        *reinterpret_cast<float4*>(smem + SM_A + row * ROW_BYTES + c4 * 16) = v;
    }

    // ---- preload B tile 0 via cp.async + its labels ----
    {
        uint32_t bdst = sbase + SM_B;
        #pragma unroll
        for (int t = 0; t < 16; t++) {
            int idx = t * NTHREADS + tid;
            int row = idx >> 5, c = idx & 31;
            cp_async16(bdst + row * ROW_BYTES + c * 16,
                       g_Etf + (size_t)(col0 + row) * K_DIM + c * 4);
        }
        CP_COMMIT();
        if (tid < NT) labS[tid] = g_lab[col0 + tid];
    }

    // row labels for this thread's 8 rows
    int labr[8];
    #pragma unroll
    for (int rt = 0; rt < 4; rt++) {
        labr[rt * 2 + 0] = g_lab[row0 + wm * 64 + rt * 16 + qr];
        labr[rt * 2 + 1] = g_lab[row0 + wm * 64 + rt * 16 + qr + 8];
    }

    float rowsum[8];
    #pragma unroll
    for (int i = 0; i < 8; i++) rowsum[i] = 0.f;

    for (int it = 0; it < N_ITERS; it++) {
        const int cur = it & 1;
        float* Bs = (float*)(smem + SM_B + cur * TILE_BYTES);

        // prefetch next tile + labels into other buffer
        if (it + 1 < N_ITERS) {
            uint32_t bdst = sbase + SM_B + (cur ^ 1) * TILE_BYTES;
            #pragma unroll
            for (int t = 0; t < 16; t++) {
                int idx = t * NTHREADS + tid;
                int row = idx >> 5, c = idx & 31;
                cp_async16(bdst + row * ROW_BYTES + c * 16,
                           g_Etf + (size_t)(col0 + (it + 1) * NT + row) * K_DIM + c * 4);
            }
            CP_COMMIT();
            if (tid < NT) labS[(cur ^ 1) * NT + tid] = g_lab[col0 + (it + 1) * NT + tid];
            CP_WAIT1();
        } else {
            CP_WAIT0();
        }
        __syncthreads();   // tile 'cur' + labels visible to everyone

        // ---- 128x128x128 warp-MMA ----
        float c[4][4][4];
        #pragma unroll
        for (int rt = 0; rt < 4; rt++)
            #pragma unroll
            for (int nt = 0; nt < 4; nt++)
                #pragma unroll
                for (int q = 0; q < 4; q++) c[rt][nt][q] = 0.f;

        #pragma unroll
        for (int ks = 0; ks < 16; ks++) {
            const int kb = ks * 8;
            uint32_t a[4][4], b[4][2];
            #pragma unroll
            for (int rt = 0; rt < 4; rt++) {
                const float* ap = As + (wm * 64 + rt * 16 + qr) * PADF + kb + qc;
                a[rt][0] = __float_as_uint(ap[0]);
                a[rt][1] = __float_as_uint(ap[8 * PADF]);
                a[rt][2] = __float_as_uint(ap[4]);
                a[rt][3] = __float_as_uint(ap[8 * PADF + 4]);
            }
            #pragma unroll
            for (int nt = 0; nt < 4; nt++) {
                const float* bp = Bs + (wn * 32 + nt * 8 + qr) * PADF + kb + qc;
                b[nt][0] = __float_as_uint(bp[0]);
                b[nt][1] = __float_as_uint(bp[4]);
            }
            #pragma unroll
            for (int rt = 0; rt < 4; rt++)
                #pragma unroll
                for (int nt = 0; nt < 4; nt++)
                    mma_tf32(c[rt][nt][0], c[rt][nt][1], c[rt][nt][2], c[rt][nt][3],
                             a[rt][0], a[rt][1], a[rt][2], a[rt][3],
                             b[nt][0], b[nt][1]);
        }

        // ---- fused epilogue: exp + per-row accumulate ----
        int labc[8];
        #pragma unroll
        for (int nt = 0; nt < 4; nt++) {
            int n0 = wn * 32 + nt * 8 + 2 * qc;
            labc[nt * 2 + 0] = labS[cur * NT + n0];
            labc[nt * 2 + 1] = labS[cur * NT + n0 + 1];
        }
        #pragma unroll
        for (int rt = 0; rt < 4; rt++) {
            #pragma unroll
            for (int nt = 0; nt < 4; nt++) {
                float t0 = c[rt][nt][0] - MARGIN;
                float t1 = c[rt][nt][1] - MARGIN;
                float t2 = c[rt][nt][2] - MARGIN;
                float t3 = c[rt][nt][3] - MARGIN;
                if (labr[rt * 2 + 0] == labc[nt * 2 + 0]) t0 = -t0;
                if (labr[rt * 2 + 0] == labc[nt * 2 + 1]) t1 = -t1;
                if (labr[rt * 2 + 1] == labc[nt * 2 + 0]) t2 = -t2;
                if (labr[rt * 2 + 1] == labc[nt * 2 + 1]) t3 = -t3;
                rowsum[rt * 2 + 0] += __expf(t0) + __expf(t1);
                rowsum[rt * 2 + 1] += __expf(t2) + __expf(t3);
            }
        }
        __syncthreads();   // everyone done with tile 'cur' before it is overwritten
    }

    // ---- deterministic reduction across quad-columns, then column-warps ----
    #pragma unroll
    for (int i = 0; i < 8; i++) {
        rowsum[i] += __shfl_xor_sync(0xFFFFFFFF, rowsum[i], 1);
        rowsum[i] += __shfl_xor_sync(0xFFFFFFFF, rowsum[i], 2);
    }
    if (qc == 0) {
        #pragma unroll
        for (int rt = 0; rt < 4; rt++) {
            red[wn * MT + wm * 64 + rt * 16 + qr]     = rowsum[rt * 2 + 0];
            red[wn * MT + wm * 64 + rt * 16 + qr + 8] = rowsum[rt * 2 + 1];
        }
    }
    __syncthreads();
    if (tid < MT) {
        float s = red[tid] + red[MT + tid] + red[2 * MT + tid] + red[3 * MT + tid];
        g_rowsum[half][row0 + tid] = s;
    }
}

// ---------------------------------------------------------------------------
// Final reduction: loss = mean_r log(rowsum0[r] + rowsum1[r])
// ---------------------------------------------------------------------------
__global__ void npair_final(float* __restrict__ out)
{
    __shared__ float red[256];
    int tid = threadIdx.x;
    float s = 0.f;
    #pragma unroll
    for (int i = 0; i < N_ROWS / 256; i++) {
        int r = i * 256 + tid;
        s += logf(g_rowsum[0][r] + g_rowsum[1][r]);
    }
    red[tid] = s;
    __syncthreads();
    for (int st = 128; st > 0; st >>= 1) {
        if (tid < st) red[tid] += red[tid + st];
        __syncthreads();
    }
    if (tid == 0) out[0] = red[0] / (float)N_ROWS;
}

extern "C" void kernel_launch(void* const* d_in, const int* in_sizes, int n_in,
                              void* d_out, int out_size)
{
    const float* E   = (const float*)d_in[0];
    const int*   lab = (const int*)d_in[1];
    float*       out = (float*)d_out;

    cudaFuncSetAttribute(npair_mma, cudaFuncAttributeMaxDynamicSharedMemorySize, SM_TOTAL);

    fix_labels<<<1, 1024>>>(lab);
    stage_tf32<<<512, 512>>>(E);
    npair_mma<<<128, NTHREADS, SM_TOTAL>>>();
    npair_final<<<1, 256>>>(out);
}

// round 8
// speedup vs baseline: 12.1000x; 1.5495x over previous
#include <cuda_runtime.h>
#include <cuda_fp16.h>
#include <cstdint>
#include <math.h>

#define N_ROWS   8192
#define K_DIM    128
#define MT       128
#define NT       128
#define HALF     4096
#define N_ITERS  (HALF / NT)      // 32
#define NTHREADS 256
#define MARGIN   0.1f

// ---- static device scratch ----
__device__ __align__(16) __half g_Eh[N_ROWS * K_DIM];  // fp16 embeddings (2 MB)
__device__ float        g_rowsum[2][N_ROWS];
__device__ int          g_lab[N_ROWS];
__device__ unsigned int g_count = 0;

// ---- smem byte offsets (fp16 tiles, 272B padded rows: 128 halfs + 8 pad) ----
#define ROW_BYTES  272
#define TILE_BYTES (MT * ROW_BYTES)              // 34816
#define SM_A       0
#define SM_B       TILE_BYTES
#define SM_LAB     (SM_B + 2 * TILE_BYTES)       // int[2][NT]
#define SM_RED     (SM_LAB + 2 * NT * 4)         // float[4][MT]
#define SM_TOTAL   (SM_RED + 4 * MT * 4)         // ~107.5 KB

__device__ __forceinline__ uint32_t smem_u32(const void* p) {
    uint32_t a;
    asm("{ .reg .u64 t; cvta.to.shared.u64 t, %1; cvt.u32.u64 %0, t; }" : "=r"(a) : "l"(p));
    return a;
}
__device__ __forceinline__ void cp_async16(uint32_t dst, const void* src) {
    asm volatile("cp.async.cg.shared.global [%0], [%1], 16;" :: "r"(dst), "l"(src) : "memory");
}
#define CP_COMMIT() asm volatile("cp.async.commit_group;" ::: "memory")
#define CP_WAIT1()  asm volatile("cp.async.wait_group 1;" ::: "memory")
#define CP_WAIT0()  asm volatile("cp.async.wait_group 0;" ::: "memory")

__device__ __forceinline__ void ldsm4(uint32_t& r0, uint32_t& r1, uint32_t& r2, uint32_t& r3,
                                      uint32_t addr) {
    asm volatile("ldmatrix.sync.aligned.m8n8.x4.shared.b16 {%0,%1,%2,%3}, [%4];"
                 : "=r"(r0), "=r"(r1), "=r"(r2), "=r"(r3) : "r"(addr));
}
__device__ __forceinline__ void mma_f16(float& c0, float& c1, float& c2, float& c3,
                                        uint32_t a0, uint32_t a1, uint32_t a2, uint32_t a3,
                                        uint32_t b0, uint32_t b1) {
    asm volatile(
        "mma.sync.aligned.m16n8k16.row.col.f32.f16.f16.f32 "
        "{%0,%1,%2,%3}, {%4,%5,%6,%7}, {%8,%9}, {%0,%1,%2,%3};"
        : "+f"(c0), "+f"(c1), "+f"(c2), "+f"(c3)
        : "r"(a0), "r"(a1), "r"(a2), "r"(a3), "r"(b0), "r"(b1));
}

// ---------------------------------------------------------------------------
// Stage: fp16-convert embeddings (all blocks) + normalize labels (block 0).
// Labels: reference asks int64 but JAX w/o x64 emits int32 -> auto-detect.
// ---------------------------------------------------------------------------
__global__ void stage(const float* __restrict__ E, const int* __restrict__ lab32)
{
    const float4* E4 = (const float4*)E;
    int t = blockIdx.x * blockDim.x + threadIdx.x;   // 0..65535
    #pragma unroll
    for (int i = 0; i < 4; i++) {
        int idx = i * 65536 + t;                     // 262144 float4 total
        float4 v = E4[idx];
        __half2 h0 = __floats2half2_rn(v.x, v.y);
        __half2 h1 = __floats2half2_rn(v.z, v.w);
        uint2 u;
        u.x = *(const uint32_t*)&h0;
        u.y = *(const uint32_t*)&h1;
        reinterpret_cast<uint2*>(g_Eh)[idx] = u;
    }
    if (blockIdx.x == 0) {
        int local = 0;
        for (int i = threadIdx.x; i < N_ROWS / 2; i += blockDim.x)
            local |= lab32[2 * i + 1];
        int any_odd = __syncthreads_or(local);
        if (any_odd) {
            for (int i = threadIdx.x; i < N_ROWS; i += blockDim.x) g_lab[i] = lab32[i];
        } else {
            for (int i = threadIdx.x; i < N_ROWS; i += blockDim.x) g_lab[i] = lab32[2 * i];
        }
    }
}

// ---------------------------------------------------------------------------
// Main: fp16 warp-MMA GEMM (ldmatrix + m16n8k16) with fused exp/row-sum
// epilogue and fused final reduction (arrival counter; deterministic).
// Grid 128 = 64 row-blocks x 2 column halves.
// ---------------------------------------------------------------------------
__global__ __launch_bounds__(NTHREADS)
void npair_mma(float* __restrict__ out)
{
    extern __shared__ char smem[];
    const uint32_t sbase = smem_u32(smem);
    int*   labS = (int*)(smem + SM_LAB);      // [2][NT]
    float* red  = (float*)(smem + SM_RED);    // [4][MT]

    const int tid = threadIdx.x;
    const int wid = tid >> 5, lid = tid & 31;
    const int wm = wid >> 2;                  // 0..1 row 64-block
    const int wn = wid & 3;                   // 0..3 col 32-block
    const int qr = lid >> 2;                  // accum frag row 0..7
    const int qc = lid & 3;                   // accum frag colpair 0..3
    const int lq = lid >> 3;                  // ldmatrix quadrant 0..3
    const int lr = lid & 7;                   // ldmatrix row 0..7

    const int rowblk = blockIdx.x >> 1;
    const int half   = blockIdx.x & 1;
    const int row0   = rowblk * MT;
    const int col0   = half * HALF;

    // per-lane ldmatrix base offsets (bytes)
    const uint32_t aBase = sbase + SM_A +
        (uint32_t)(wm * 64 + (lq & 1) * 8 + lr) * ROW_BYTES + (uint32_t)(lq >> 1) * 16;
    const uint32_t bBase0 = (uint32_t)(wn * 32 + (lq >> 1) * 8 + lr) * ROW_BYTES +
                            (uint32_t)(lq & 1) * 16;

    // ---- load resident A tile (128 x 128 half) ----
    #pragma unroll
    for (int t = 0; t < 8; t++) {
        int idx = t * NTHREADS + tid;         // 0..2047 16B chunks
        int row = idx >> 4, c = idx & 15;
        uint4 v = *reinterpret_cast<const uint4*>(
            (const char*)g_Eh + ((size_t)(row0 + row) * K_DIM + c * 8) * 2);
        *reinterpret_cast<uint4*>(smem + SM_A + row * ROW_BYTES + c * 16) = v;
    }

    // ---- preload B tile 0 via cp.async + labels ----
    {
        uint32_t bdst = sbase + SM_B;
        #pragma unroll
        for (int t = 0; t < 8; t++) {
            int idx = t * NTHREADS + tid;
            int row = idx >> 4, c = idx & 15;
            cp_async16(bdst + row * ROW_BYTES + c * 16,
                       g_Eh + (size_t)(col0 + row) * K_DIM + c * 8);
        }
        CP_COMMIT();
        if (tid < NT) labS[tid] = g_lab[col0 + tid];
    }

    int labr[8];
    #pragma unroll
    for (int rt = 0; rt < 4; rt++) {
        labr[rt * 2 + 0] = g_lab[row0 + wm * 64 + rt * 16 + qr];
        labr[rt * 2 + 1] = g_lab[row0 + wm * 64 + rt * 16 + qr + 8];
    }

    float rowsum[8];
    #pragma unroll
    for (int i = 0; i < 8; i++) rowsum[i] = 0.f;

    for (int it = 0; it < N_ITERS; it++) {
        const int cur = it & 1;

        if (it + 1 < N_ITERS) {
            uint32_t bdst = sbase + SM_B + (cur ^ 1) * TILE_BYTES;
            #pragma unroll
            for (int t = 0; t < 8; t++) {
                int idx = t * NTHREADS + tid;
                int row = idx >> 4, c = idx & 15;
                cp_async16(bdst + row * ROW_BYTES + c * 16,
                           g_Eh + (size_t)(col0 + (it + 1) * NT + row) * K_DIM + c * 8);
            }
            CP_COMMIT();
            if (tid < NT) labS[(cur ^ 1) * NT + tid] = g_lab[col0 + (it + 1) * NT + tid];
            CP_WAIT1();
        } else {
            CP_WAIT0();
        }
        __syncthreads();

        // ---- 128x128x128 fp16 warp-MMA ----
        float c[4][4][4];
        #pragma unroll
        for (int rt = 0; rt < 4; rt++)
            #pragma unroll
            for (int nt = 0; nt < 4; nt++)
                #pragma unroll
                for (int q = 0; q < 4; q++) c[rt][nt][q] = 0.f;

        const uint32_t bBase = sbase + SM_B + cur * TILE_BYTES + bBase0;

        #pragma unroll
        for (int ks = 0; ks < 8; ks++) {
            uint32_t a[4][4], b[4][2];
            #pragma unroll
            for (int rt = 0; rt < 4; rt++)
                ldsm4(a[rt][0], a[rt][1], a[rt][2], a[rt][3],
                      aBase + rt * 16 * ROW_BYTES + ks * 32);
            #pragma unroll
            for (int p = 0; p < 2; p++) {
                uint32_t r0, r1, r2, r3;
                ldsm4(r0, r1, r2, r3, bBase + p * 16 * ROW_BYTES + ks * 32);
                b[2 * p][0] = r0; b[2 * p][1] = r1;
                b[2 * p + 1][0] = r2; b[2 * p + 1][1] = r3;
            }
            #pragma unroll
            for (int rt = 0; rt < 4; rt++)
                #pragma unroll
                for (int nt = 0; nt < 4; nt++)
                    mma_f16(c[rt][nt][0], c[rt][nt][1], c[rt][nt][2], c[rt][nt][3],
                            a[rt][0], a[rt][1], a[rt][2], a[rt][3],
                            b[nt][0], b[nt][1]);
        }

        // ---- fused epilogue ----
        int labc[8];
        #pragma unroll
        for (int nt = 0; nt < 4; nt++) {
            int n0 = wn * 32 + nt * 8 + 2 * qc;
            labc[nt * 2 + 0] = labS[cur * NT + n0];
            labc[nt * 2 + 1] = labS[cur * NT + n0 + 1];
        }
        #pragma unroll
        for (int rt = 0; rt < 4; rt++) {
            #pragma unroll
            for (int nt = 0; nt < 4; nt++) {
                float t0 = c[rt][nt][0] - MARGIN;
                float t1 = c[rt][nt][1] - MARGIN;
                float t2 = c[rt][nt][2] - MARGIN;
                float t3 = c[rt][nt][3] - MARGIN;
                if (labr[rt * 2 + 0] == labc[nt * 2 + 0]) t0 = -t0;
                if (labr[rt * 2 + 0] == labc[nt * 2 + 1]) t1 = -t1;
                if (labr[rt * 2 + 1] == labc[nt * 2 + 0]) t2 = -t2;
                if (labr[rt * 2 + 1] == labc[nt * 2 + 1]) t3 = -t3;
                rowsum[rt * 2 + 0] += __expf(t0) + __expf(t1);
                rowsum[rt * 2 + 1] += __expf(t2) + __expf(t3);
            }
        }
        __syncthreads();
    }

    // ---- deterministic reduction: quad-cols -> column-warps -> gmem ----
    #pragma unroll
    for (int i = 0; i < 8; i++) {
        rowsum[i] += __shfl_xor_sync(0xFFFFFFFF, rowsum[i], 1);
        rowsum[i] += __shfl_xor_sync(0xFFFFFFFF, rowsum[i], 2);
    }
    if (qc == 0) {
        #pragma unroll
        for (int rt = 0; rt < 4; rt++) {
            red[wn * MT + wm * 64 + rt * 16 + qr]     = rowsum[rt * 2 + 0];
            red[wn * MT + wm * 64 + rt * 16 + qr + 8] = rowsum[rt * 2 + 1];
        }
    }
    __syncthreads();
    if (tid < MT) {
        float s = red[tid] + red[MT + tid] + red[2 * MT + tid] + red[3 * MT + tid];
        g_rowsum[half][row0 + tid] = s;
    }

    // ---- fused final reduction: last-arriving CTA computes the loss ----
    __shared__ int lastFlag;
    if (tid == 0) {
        __threadfence();
        unsigned int old = atomicAdd(&g_count, 1u);
        lastFlag = (old == (unsigned)(gridDim.x - 1));
    }
    __syncthreads();
    if (lastFlag) {
        __threadfence();
        float s = 0.f;
        #pragma unroll
        for (int i = 0; i < N_ROWS / NTHREADS; i++) {
            int r = i * NTHREADS + tid;      // fixed order per thread
            s += logf(g_rowsum[0][r] + g_rowsum[1][r]);
        }
        float* redf = (float*)(smem + SM_RED);
        redf[tid] = s;
        __syncthreads();
        for (int st = 128; st > 0; st >>= 1) {
            if (tid < st) redf[tid] += redf[tid + st];
            __syncthreads();
        }
        if (tid == 0) {
            out[0] = redf[0] / (float)N_ROWS;
            g_count = 0;                     // reset for next (graph) launch
        }
    }
}

extern "C" void kernel_launch(void* const* d_in, const int* in_sizes, int n_in,
                              void* d_out, int out_size)
{
    const float* E   = (const float*)d_in[0];
    const int*   lab = (const int*)d_in[1];
    float*       out = (float*)d_out;

    cudaFuncSetAttribute(npair_mma, cudaFuncAttributeMaxDynamicSharedMemorySize, SM_TOTAL);

    stage<<<256, 256>>>(E, lab);
    npair_mma<<<128, NTHREADS, SM_TOTAL>>>(out);
}

// round 9
// speedup vs baseline: 12.1250x; 1.0021x over previous
#include <cuda_runtime.h>
#include <cuda_fp16.h>
#include <cstdint>
#include <math.h>

#define N_ROWS   8192
#define K_DIM    128
#define MT       128
#define NT       128
#define HALF     4096
#define N_ITERS  (HALF / NT)      // 32
#define NTHREADS 512              // 16 warps
#define MARGIN   0.1f

// ---- static device scratch ----
__device__ __align__(16) __half g_Eh[N_ROWS * K_DIM];  // fp16 embeddings (2 MB)
__device__ float        g_rowsum[2][N_ROWS];
__device__ int          g_lab[N_ROWS];
__device__ unsigned int g_count = 0;

// ---- smem byte offsets (fp16 tiles, 272B padded rows: 128 halfs + 8 pad) ----
#define ROW_BYTES  272
#define TILE_BYTES (MT * ROW_BYTES)              // 34816
#define SM_A       0
#define SM_B       TILE_BYTES
#define SM_LAB     (SM_B + 2 * TILE_BYTES)       // int[2][NT]
#define SM_RED     (SM_LAB + 2 * NT * 4)         // float[4][MT] = 512 floats
#define SM_TOTAL   (SM_RED + 4 * MT * 4)         // ~107.5 KB

__device__ __forceinline__ uint32_t smem_u32(const void* p) {
    uint32_t a;
    asm("{ .reg .u64 t; cvta.to.shared.u64 t, %1; cvt.u32.u64 %0, t; }" : "=r"(a) : "l"(p));
    return a;
}
__device__ __forceinline__ void cp_async16(uint32_t dst, const void* src) {
    asm volatile("cp.async.cg.shared.global [%0], [%1], 16;" :: "r"(dst), "l"(src) : "memory");
}
#define CP_COMMIT() asm volatile("cp.async.commit_group;" ::: "memory")
#define CP_WAIT1()  asm volatile("cp.async.wait_group 1;" ::: "memory")
#define CP_WAIT0()  asm volatile("cp.async.wait_group 0;" ::: "memory")

__device__ __forceinline__ void ldsm4(uint32_t& r0, uint32_t& r1, uint32_t& r2, uint32_t& r3,
                                      uint32_t addr) {
    asm volatile("ldmatrix.sync.aligned.m8n8.x4.shared.b16 {%0,%1,%2,%3}, [%4];"
                 : "=r"(r0), "=r"(r1), "=r"(r2), "=r"(r3) : "r"(addr));
}
__device__ __forceinline__ void mma_f16(float& c0, float& c1, float& c2, float& c3,
                                        uint32_t a0, uint32_t a1, uint32_t a2, uint32_t a3,
                                        uint32_t b0, uint32_t b1) {
    asm volatile(
        "mma.sync.aligned.m16n8k16.row.col.f32.f16.f16.f32 "
        "{%0,%1,%2,%3}, {%4,%5,%6,%7}, {%8,%9}, {%0,%1,%2,%3};"
        : "+f"(c0), "+f"(c1), "+f"(c2), "+f"(c3)
        : "r"(a0), "r"(a1), "r"(a2), "r"(a3), "r"(b0), "r"(b1));
}

// ---------------------------------------------------------------------------
// Stage: fp16-convert embeddings (all blocks) + normalize labels (block 0).
// Labels: reference asks int64 but JAX w/o x64 emits int32 -> auto-detect.
// ---------------------------------------------------------------------------
__global__ void stage(const float* __restrict__ E, const int* __restrict__ lab32)
{
    const float4* E4 = (const float4*)E;
    int t = blockIdx.x * blockDim.x + threadIdx.x;   // 0..65535
    #pragma unroll
    for (int i = 0; i < 4; i++) {
        int idx = i * 65536 + t;                     // 262144 float4 total
        float4 v = E4[idx];
        __half2 h0 = __floats2half2_rn(v.x, v.y);
        __half2 h1 = __floats2half2_rn(v.z, v.w);
        uint2 u;
        u.x = *(const uint32_t*)&h0;
        u.y = *(const uint32_t*)&h1;
        reinterpret_cast<uint2*>(g_Eh)[idx] = u;
    }
    if (blockIdx.x == 0) {
        int local = 0;
        for (int i = threadIdx.x; i < N_ROWS / 2; i += blockDim.x)
            local |= lab32[2 * i + 1];
        int any_odd = __syncthreads_or(local);
        if (any_odd) {
            for (int i = threadIdx.x; i < N_ROWS; i += blockDim.x) g_lab[i] = lab32[i];
        } else {
            for (int i = threadIdx.x; i < N_ROWS; i += blockDim.x) g_lab[i] = lab32[2 * i];
        }
    }
}

// ---------------------------------------------------------------------------
// Main: fp16 warp-MMA GEMM, 16 warps x (32x32) warp tiles, fused epilogue,
// fused deterministic final reduction. Grid 128 = 64 row-blocks x 2 halves.
// ---------------------------------------------------------------------------
__global__ __launch_bounds__(NTHREADS, 1)
void npair_mma(float* __restrict__ out)
{
    extern __shared__ char smem[];
    const uint32_t sbase = smem_u32(smem);
    int*   labS = (int*)(smem + SM_LAB);      // [2][NT]
    float* red  = (float*)(smem + SM_RED);    // [4][MT]

    const int tid = threadIdx.x;
    const int wid = tid >> 5, lid = tid & 31;
    const int wm = wid >> 2;                  // 0..3 row 32-block
    const int wn = wid & 3;                   // 0..3 col 32-block
    const int qr = lid >> 2;                  // accum frag row 0..7
    const int qc = lid & 3;                   // accum frag colpair 0..3
    const int lq = lid >> 3;                  // ldmatrix quadrant 0..3
    const int lr = lid & 7;                   // ldmatrix row 0..7

    const int rowblk = blockIdx.x >> 1;
    const int half   = blockIdx.x & 1;
    const int row0   = rowblk * MT;
    const int col0   = half * HALF;

    // per-lane ldmatrix base offsets (bytes)
    const uint32_t aBase = sbase + SM_A +
        (uint32_t)(wm * 32 + (lq & 1) * 8 + lr) * ROW_BYTES + (uint32_t)(lq >> 1) * 16;
    const uint32_t bBase0 = (uint32_t)(wn * 32 + (lq >> 1) * 8 + lr) * ROW_BYTES +
                            (uint32_t)(lq & 1) * 16;

    // ---- load resident A tile (128 x 128 half) ----
    #pragma unroll
    for (int t = 0; t < 4; t++) {
        int idx = t * NTHREADS + tid;         // 0..2047 16B chunks
        int row = idx >> 4, c = idx & 15;
        uint4 v = *reinterpret_cast<const uint4*>(
            (const char*)g_Eh + ((size_t)(row0 + row) * K_DIM + c * 8) * 2);
        *reinterpret_cast<uint4*>(smem + SM_A + row * ROW_BYTES + c * 16) = v;
    }

    // ---- preload B tile 0 via cp.async + labels ----
    {
        uint32_t bdst = sbase + SM_B;
        #pragma unroll
        for (int t = 0; t < 4; t++) {
            int idx = t * NTHREADS + tid;
            int row = idx >> 4, c = idx & 15;
            cp_async16(bdst + row * ROW_BYTES + c * 16,
                       g_Eh + (size_t)(col0 + row) * K_DIM + c * 8);
        }
        CP_COMMIT();
        if (tid < NT) labS[tid] = g_lab[col0 + tid];
    }

    int labr[4];
    #pragma unroll
    for (int rt = 0; rt < 2; rt++) {
        labr[rt * 2 + 0] = g_lab[row0 + wm * 32 + rt * 16 + qr];
        labr[rt * 2 + 1] = g_lab[row0 + wm * 32 + rt * 16 + qr + 8];
    }

    float rowsum[4];
    #pragma unroll
    for (int i = 0; i < 4; i++) rowsum[i] = 0.f;

    for (int it = 0; it < N_ITERS; it++) {
        const int cur = it & 1;

        if (it + 1 < N_ITERS) {
            uint32_t bdst = sbase + SM_B + (cur ^ 1) * TILE_BYTES;
            #pragma unroll
            for (int t = 0; t < 4; t++) {
                int idx = t * NTHREADS + tid;
                int row = idx >> 4, c = idx & 15;
                cp_async16(bdst + row * ROW_BYTES + c * 16,
                           g_Eh + (size_t)(col0 + (it + 1) * NT + row) * K_DIM + c * 8);
            }
            CP_COMMIT();
            if (tid < NT) labS[(cur ^ 1) * NT + tid] = g_lab[col0 + (it + 1) * NT + tid];
            CP_WAIT1();
        } else {
            CP_WAIT0();
        }
        __syncthreads();

        // ---- 128x128x128 fp16 warp-MMA (per warp: 32x32) ----
        float c[2][4][4];
        #pragma unroll
        for (int rt = 0; rt < 2; rt++)
            #pragma unroll
            for (int nt = 0; nt < 4; nt++)
                #pragma unroll
                for (int q = 0; q < 4; q++) c[rt][nt][q] = 0.f;

        const uint32_t bBase = sbase + SM_B + cur * TILE_BYTES + bBase0;

        #pragma unroll
        for (int ks = 0; ks < 8; ks++) {
            uint32_t a[2][4], b[4][2];
            #pragma unroll
            for (int rt = 0; rt < 2; rt++)
                ldsm4(a[rt][0], a[rt][1], a[rt][2], a[rt][3],
                      aBase + rt * 16 * ROW_BYTES + ks * 32);
            #pragma unroll
            for (int p = 0; p < 2; p++) {
                uint32_t r0, r1, r2, r3;
                ldsm4(r0, r1, r2, r3, bBase + p * 16 * ROW_BYTES + ks * 32);
                b[2 * p][0] = r0; b[2 * p][1] = r1;
                b[2 * p + 1][0] = r2; b[2 * p + 1][1] = r3;
            }
            #pragma unroll
            for (int rt = 0; rt < 2; rt++)
                #pragma unroll
                for (int nt = 0; nt < 4; nt++)
                    mma_f16(c[rt][nt][0], c[rt][nt][1], c[rt][nt][2], c[rt][nt][3],
                            a[rt][0], a[rt][1], a[rt][2], a[rt][3],
                            b[nt][0], b[nt][1]);
        }

        // ---- fused epilogue: exp + per-row accumulate ----
        int labc[8];
        #pragma unroll
        for (int nt = 0; nt < 4; nt++) {
            int n0 = wn * 32 + nt * 8 + 2 * qc;
            labc[nt * 2 + 0] = labS[cur * NT + n0];
            labc[nt * 2 + 1] = labS[cur * NT + n0 + 1];
        }
        #pragma unroll
        for (int rt = 0; rt < 2; rt++) {
            #pragma unroll
            for (int nt = 0; nt < 4; nt++) {
                float t0 = c[rt][nt][0] - MARGIN;
                float t1 = c[rt][nt][1] - MARGIN;
                float t2 = c[rt][nt][2] - MARGIN;
                float t3 = c[rt][nt][3] - MARGIN;
                if (labr[rt * 2 + 0] == labc[nt * 2 + 0]) t0 = -t0;
                if (labr[rt * 2 + 0] == labc[nt * 2 + 1]) t1 = -t1;
                if (labr[rt * 2 + 1] == labc[nt * 2 + 0]) t2 = -t2;
                if (labr[rt * 2 + 1] == labc[nt * 2 + 1]) t3 = -t3;
                rowsum[rt * 2 + 0] += __expf(t0) + __expf(t1);
                rowsum[rt * 2 + 1] += __expf(t2) + __expf(t3);
            }
        }
        __syncthreads();
    }

    // ---- deterministic reduction: quad-cols -> column-warps -> gmem ----
    #pragma unroll
    for (int i = 0; i < 4; i++) {
        rowsum[i] += __shfl_xor_sync(0xFFFFFFFF, rowsum[i], 1);
        rowsum[i] += __shfl_xor_sync(0xFFFFFFFF, rowsum[i], 2);
    }
    if (qc == 0) {
        #pragma unroll
        for (int rt = 0; rt < 2; rt++) {
            red[wn * MT + wm * 32 + rt * 16 + qr]     = rowsum[rt * 2 + 0];
            red[wn * MT + wm * 32 + rt * 16 + qr + 8] = rowsum[rt * 2 + 1];
        }
    }
    __syncthreads();
    if (tid < MT) {
        float s = red[tid] + red[MT + tid] + red[2 * MT + tid] + red[3 * MT + tid];
        g_rowsum[half][row0 + tid] = s;
    }

    // ---- fused final reduction: last-arriving CTA computes the loss ----
    __shared__ int lastFlag;
    if (tid == 0) {
        __threadfence();
        unsigned int old = atomicAdd(&g_count, 1u);
        lastFlag = (old == (unsigned)(gridDim.x - 1));
    }
    __syncthreads();
    if (lastFlag) {
        __threadfence();
        float s = 0.f;
        #pragma unroll
        for (int i = 0; i < N_ROWS / NTHREADS; i++) {
            int r = i * NTHREADS + tid;      // fixed order per thread
            s += logf(g_rowsum[0][r] + g_rowsum[1][r]);
        }
        float* redf = (float*)(smem + SM_RED);
        redf[tid] = s;
        __syncthreads();
        for (int st = NTHREADS / 2; st > 0; st >>= 1) {
            if (tid < st) redf[tid] += redf[tid + st];
            __syncthreads();
        }
        if (tid == 0) {
            out[0] = redf[0] / (float)N_ROWS;
            g_count = 0;                     // reset for next (graph) launch
        }
    }
}

extern "C" void kernel_launch(void* const* d_in, const int* in_sizes, int n_in,
                              void* d_out, int out_size)
{
    const float* E   = (const float*)d_in[0];
    const int*   lab = (const int*)d_in[1];
    float*       out = (float*)d_out;

    cudaFuncSetAttribute(npair_mma, cudaFuncAttributeMaxDynamicSharedMemorySize, SM_TOTAL);

    stage<<<256, 256>>>(E, lab);
    npair_mma<<<128, NTHREADS, SM_TOTAL>>>(out);
}

// round 10
// speedup vs baseline: 14.6686x; 1.2098x over previous
#include <cuda_runtime.h>
#include <cuda_fp16.h>
#include <cstdint>
#include <math.h>

#define N_ROWS   8192
#define K_DIM    128
#define MT       128
#define NT       128
#define HALF     4096
#define N_ITERS  (HALF / NT)      // 32
#define NTHREADS 512              // 16 warps
#define LOG2E    1.4426950408889634f
#define SCALE_H  1.2011224087864498f   // sqrt(log2e): GEMM then yields sim*log2e
#define M_L2     (0.1f * LOG2E)        // margin in log2 domain

// ---- static device scratch ----
__device__ __align__(16) __half g_Eh[N_ROWS * K_DIM];  // fp16(E * sqrt(log2e))
__device__ float        g_rowsum[2][N_ROWS];
__device__ int          g_lab[N_ROWS];
__device__ unsigned int g_count = 0;

// ---- smem byte offsets (fp16 tiles, 272B padded rows) ----
#define ROW_BYTES  272
#define TILE_BYTES (MT * ROW_BYTES)              // 34816
#define SM_A       0
#define SM_B       TILE_BYTES                    // 3 buffers
#define SM_LAB     (SM_B + 3 * TILE_BYTES)       // int[3][NT]
#define SM_RED     (SM_LAB + 3 * NT * 4)         // float[4][MT]
#define SM_TOTAL   (SM_RED + 4 * MT * 4)         // ~139.5 KB

__device__ __forceinline__ uint32_t smem_u32(const void* p) {
    uint32_t a;
    asm("{ .reg .u64 t; cvta.to.shared.u64 t, %1; cvt.u32.u64 %0, t; }" : "=r"(a) : "l"(p));
    return a;
}
__device__ __forceinline__ void cp_async16(uint32_t dst, const void* src) {
    asm volatile("cp.async.cg.shared.global [%0], [%1], 16;" :: "r"(dst), "l"(src) : "memory");
}
#define CP_COMMIT() asm volatile("cp.async.commit_group;" ::: "memory")
#define CP_WAIT1()  asm volatile("cp.async.wait_group 1;" ::: "memory")
#define CP_WAIT0()  asm volatile("cp.async.wait_group 0;" ::: "memory")

__device__ __forceinline__ void ldsm4(uint32_t& r0, uint32_t& r1, uint32_t& r2, uint32_t& r3,
                                      uint32_t addr) {
    asm volatile("ldmatrix.sync.aligned.m8n8.x4.shared.b16 {%0,%1,%2,%3}, [%4];"
                 : "=r"(r0), "=r"(r1), "=r"(r2), "=r"(r3) : "r"(addr));
}
__device__ __forceinline__ void mma_f16(float& c0, float& c1, float& c2, float& c3,
                                        uint32_t a0, uint32_t a1, uint32_t a2, uint32_t a3,
                                        uint32_t b0, uint32_t b1) {
    asm volatile(
        "mma.sync.aligned.m16n8k16.row.col.f32.f16.f16.f32 "
        "{%0,%1,%2,%3}, {%4,%5,%6,%7}, {%8,%9}, {%0,%1,%2,%3};"
        : "+f"(c0), "+f"(c1), "+f"(c2), "+f"(c3)
        : "r"(a0), "r"(a1), "r"(a2), "r"(a3), "r"(b0), "r"(b1));
}
__device__ __forceinline__ float ex2(float x) {
    float r;
    asm("ex2.approx.f32 %0, %1;" : "=f"(r) : "f"(x));
    return r;
}

// ---------------------------------------------------------------------------
// Stage: fp16-convert scaled embeddings + normalize labels (block 0).
// Labels: reference asks int64 but JAX w/o x64 emits int32 -> auto-detect.
// ---------------------------------------------------------------------------
__global__ void stage(const float* __restrict__ E, const int* __restrict__ lab32)
{
    const float4* E4 = (const float4*)E;
    int t = blockIdx.x * blockDim.x + threadIdx.x;   // 0..65535
    #pragma unroll
    for (int i = 0; i < 4; i++) {
        int idx = i * 65536 + t;                     // 262144 float4 total
        float4 v = E4[idx];
        __half2 h0 = __floats2half2_rn(v.x * SCALE_H, v.y * SCALE_H);
        __half2 h1 = __floats2half2_rn(v.z * SCALE_H, v.w * SCALE_H);
        uint2 u;
        u.x = *(const uint32_t*)&h0;
        u.y = *(const uint32_t*)&h1;
        reinterpret_cast<uint2*>(g_Eh)[idx] = u;
    }
    if (blockIdx.x == 0) {
        int local = 0;
        for (int i = threadIdx.x; i < N_ROWS / 2; i += blockDim.x)
            local |= lab32[2 * i + 1];
        int any_odd = __syncthreads_or(local);
        if (any_odd) {
            for (int i = threadIdx.x; i < N_ROWS; i += blockDim.x) g_lab[i] = lab32[i];
        } else {
            for (int i = threadIdx.x; i < N_ROWS; i += blockDim.x) g_lab[i] = lab32[2 * i];
        }
    }
}

// ---------------------------------------------------------------------------
// Main: fp16 warp-MMA, A fragments register-resident, 3-deep B pipeline
// (one barrier/tile), fused ex2 epilogue + deterministic final reduction.
// Grid 128 = 64 row-blocks x 2 column halves.
// ---------------------------------------------------------------------------
__global__ __launch_bounds__(NTHREADS, 1)
void npair_mma(float* __restrict__ out)
{
    extern __shared__ char smem[];
    const uint32_t sbase = smem_u32(smem);
    int*   labS = (int*)(smem + SM_LAB);      // [3][NT]
    float* red  = (float*)(smem + SM_RED);    // [4][MT]

    const int tid = threadIdx.x;
    const int wid = tid >> 5, lid = tid & 31;
    const int wm = wid >> 2;                  // 0..3 row 32-block
    const int wn = wid & 3;                   // 0..3 col 32-block
    const int qr = lid >> 2;                  // accum frag row 0..7
    const int qc = lid & 3;                   // accum frag colpair 0..3
    const int lq = lid >> 3;                  // ldmatrix quadrant 0..3
    const int lr = lid & 7;                   // ldmatrix row 0..7

    const int rowblk = blockIdx.x >> 1;
    const int half   = blockIdx.x & 1;
    const int row0   = rowblk * MT;
    const int col0   = half * HALF;

    const uint32_t aBase = sbase + SM_A +
        (uint32_t)(wm * 32 + (lq & 1) * 8 + lr) * ROW_BYTES + (uint32_t)(lq >> 1) * 16;
    const uint32_t bBase0 = (uint32_t)(wn * 32 + (lq >> 1) * 8 + lr) * ROW_BYTES +
                            (uint32_t)(lq & 1) * 16;

    // ---- load A tile to smem ----
    #pragma unroll
    for (int t = 0; t < 4; t++) {
        int idx = t * NTHREADS + tid;         // 0..2047 16B chunks
        int row = idx >> 4, c = idx & 15;
        uint4 v = *reinterpret_cast<const uint4*>(
            (const char*)g_Eh + ((size_t)(row0 + row) * K_DIM + c * 8) * 2);
        *reinterpret_cast<uint4*>(smem + SM_A + row * ROW_BYTES + c * 16) = v;
    }

    // ---- prefetch B tiles 0 and 1 + labels ----
    #pragma unroll
    for (int j = 0; j < 2; j++) {
        uint32_t bdst = sbase + SM_B + j * TILE_BYTES;
        #pragma unroll
        for (int t = 0; t < 4; t++) {
            int idx = t * NTHREADS + tid;
            int row = idx >> 4, c = idx & 15;
            cp_async16(bdst + row * ROW_BYTES + c * 16,
                       g_Eh + (size_t)(col0 + j * NT + row) * K_DIM + c * 8);
        }
        CP_COMMIT();
        if (tid < NT) labS[j * NT + tid] = g_lab[col0 + j * NT + tid];
    }

    __syncthreads();   // A tile visible

    // ---- hoist A fragments to registers (reused for all 32 tiles) ----
    uint32_t afr[8][2][4];
    #pragma unroll
    for (int ks = 0; ks < 8; ks++)
        #pragma unroll
        for (int rt = 0; rt < 2; rt++)
            ldsm4(afr[ks][rt][0], afr[ks][rt][1], afr[ks][rt][2], afr[ks][rt][3],
                  aBase + rt * 16 * ROW_BYTES + ks * 32);

    int labr[4];
    #pragma unroll
    for (int rt = 0; rt < 2; rt++) {
        labr[rt * 2 + 0] = g_lab[row0 + wm * 32 + rt * 16 + qr];
        labr[rt * 2 + 1] = g_lab[row0 + wm * 32 + rt * 16 + qr + 8];
    }

    float rowsum[4] = {0.f, 0.f, 0.f, 0.f};

    for (int it = 0; it < N_ITERS; it++) {
        const int cur = it % 3;

        if (it < N_ITERS - 2) CP_WAIT1(); else CP_WAIT0();
        __syncthreads();   // tile 'it' visible; all readers of tile it-1 done

        // prefetch tile it+2 into buffer (it+2)%3  (== (it-1)%3, now safe)
        if (it + 2 < N_ITERS) {
            const int nxt = (it + 2) % 3;
            uint32_t bdst = sbase + SM_B + nxt * TILE_BYTES;
            #pragma unroll
            for (int t = 0; t < 4; t++) {
                int idx = t * NTHREADS + tid;
                int row = idx >> 4, c = idx & 15;
                cp_async16(bdst + row * ROW_BYTES + c * 16,
                           g_Eh + (size_t)(col0 + (it + 2) * NT + row) * K_DIM + c * 8);
            }
            CP_COMMIT();
            if (tid < NT) labS[nxt * NT + tid] = g_lab[col0 + (it + 2) * NT + tid];
        }

        // ---- 128x128x128 fp16 warp-MMA (per warp: 32x32, A from regs) ----
        float c[2][4][4];
        #pragma unroll
        for (int rt = 0; rt < 2; rt++)
            #pragma unroll
            for (int nt = 0; nt < 4; nt++)
                #pragma unroll
                for (int q = 0; q < 4; q++) c[rt][nt][q] = 0.f;

        const uint32_t bBase = sbase + SM_B + cur * TILE_BYTES + bBase0;

        #pragma unroll
        for (int ks = 0; ks < 8; ks++) {
            uint32_t b[4][2];
            #pragma unroll
            for (int p = 0; p < 2; p++) {
                uint32_t r0, r1, r2, r3;
                ldsm4(r0, r1, r2, r3, bBase + p * 16 * ROW_BYTES + ks * 32);
                b[2 * p][0] = r0; b[2 * p][1] = r1;
                b[2 * p + 1][0] = r2; b[2 * p + 1][1] = r3;
            }
            #pragma unroll
            for (int rt = 0; rt < 2; rt++)
                #pragma unroll
                for (int nt = 0; nt < 4; nt++)
                    mma_f16(c[rt][nt][0], c[rt][nt][1], c[rt][nt][2], c[rt][nt][3],
                            afr[ks][rt][0], afr[ks][rt][1], afr[ks][rt][2], afr[ks][rt][3],
                            b[nt][0], b[nt][1]);
        }

        // ---- fused epilogue: sim*log2e already; ex2 with sign-flip via XOR ----
        int labc[8];
        #pragma unroll
        for (int nt = 0; nt < 4; nt++) {
            int n0 = wn * 32 + nt * 8 + 2 * qc;
            labc[nt * 2 + 0] = labS[cur * NT + n0];
            labc[nt * 2 + 1] = labS[cur * NT + n0 + 1];
        }
        #pragma unroll
        for (int rt = 0; rt < 2; rt++) {
            #pragma unroll
            for (int nt = 0; nt < 4; nt++) {
                float u0 = c[rt][nt][0] - M_L2;
                float u1 = c[rt][nt][1] - M_L2;
                float u2 = c[rt][nt][2] - M_L2;
                float u3 = c[rt][nt][3] - M_L2;
                uint32_t f0 = (labr[rt * 2 + 0] == labc[nt * 2 + 0]) ? 0x80000000u : 0u;
                uint32_t f1 = (labr[rt * 2 + 0] == labc[nt * 2 + 1]) ? 0x80000000u : 0u;
                uint32_t f2 = (labr[rt * 2 + 1] == labc[nt * 2 + 0]) ? 0x80000000u : 0u;
                uint32_t f3 = (labr[rt * 2 + 1] == labc[nt * 2 + 1]) ? 0x80000000u : 0u;
                float e0 = ex2(__uint_as_float(__float_as_uint(u0) ^ f0));
                float e1 = ex2(__uint_as_float(__float_as_uint(u1) ^ f1));
                float e2 = ex2(__uint_as_float(__float_as_uint(u2) ^ f2));
                float e3 = ex2(__uint_as_float(__float_as_uint(u3) ^ f3));
                rowsum[rt * 2 + 0] += e0 + e1;
                rowsum[rt * 2 + 1] += e2 + e3;
            }
        }
    }

    // ---- deterministic reduction: quad-cols -> column-warps -> gmem ----
    #pragma unroll
    for (int i = 0; i < 4; i++) {
        rowsum[i] += __shfl_xor_sync(0xFFFFFFFF, rowsum[i], 1);
        rowsum[i] += __shfl_xor_sync(0xFFFFFFFF, rowsum[i], 2);
    }
    __syncthreads();   // all tile reads done before red[] reuse below
    if (qc == 0) {
        #pragma unroll
        for (int rt = 0; rt < 2; rt++) {
            red[wn * MT + wm * 32 + rt * 16 + qr]     = rowsum[rt * 2 + 0];
            red[wn * MT + wm * 32 + rt * 16 + qr + 8] = rowsum[rt * 2 + 1];
        }
    }
    __syncthreads();
    if (tid < MT) {
        float s = red[tid] + red[MT + tid] + red[2 * MT + tid] + red[3 * MT + tid];
        g_rowsum[half][row0 + tid] = s;
    }

    // ---- fused final reduction: last-arriving CTA computes the loss ----
    __shared__ int lastFlag;
    if (tid == 0) {
        __threadfence();
        unsigned int old = atomicAdd(&g_count, 1u);
        lastFlag = (old == (unsigned)(gridDim.x - 1));
    }
    __syncthreads();
    if (lastFlag) {
        __threadfence();
        float s = 0.f;
        #pragma unroll
        for (int i = 0; i < N_ROWS / NTHREADS; i++) {
            int r = i * NTHREADS + tid;      // fixed order per thread
            s += logf(g_rowsum[0][r] + g_rowsum[1][r]);
        }
        float* redf = (float*)(smem + SM_RED);
        redf[tid] = s;
        __syncthreads();
        for (int st = NTHREADS / 2; st > 0; st >>= 1) {
            if (tid < st) redf[tid] += redf[tid + st];
            __syncthreads();
        }
        if (tid == 0) {
            out[0] = redf[0] / (float)N_ROWS;
            g_count = 0;                     // reset for next (graph) launch
        }
    }
}

extern "C" void kernel_launch(void* const* d_in, const int* in_sizes, int n_in,
                              void* d_out, int out_size)
{
    const float* E   = (const float*)d_in[0];
    const int*   lab = (const int*)d_in[1];
    float*       out = (float*)d_out;

    cudaFuncSetAttribute(npair_mma, cudaFuncAttributeMaxDynamicSharedMemorySize, SM_TOTAL);

    stage<<<256, 256>>>(E, lab);
    npair_mma<<<128, NTHREADS, SM_TOTAL>>>(out);
}

// round 11
// speedup vs baseline: 15.5594x; 1.0607x over previous
#include <cuda_runtime.h>
#include <cuda_fp16.h>
#include <cstdint>
#include <math.h>

#define N_ROWS   8192
#define K_DIM    128
#define MT       128
#define NT       128
#define NTHREADS 512              // 16 warps
#define GRID     148
#define RBLOCKS  (N_ROWS / MT)    // 64
#define CTILES   (N_ROWS / NT)    // 64
#define TOTAL_T  (RBLOCKS * CTILES)  // 4096
#define LOG2E    1.4426950408889634f
#define SCALE_H  1.2011224087864498f   // sqrt(log2e): GEMM yields sim*log2e
#define M_L2     (0.1f * LOG2E)

// ---- static device scratch ----
__device__ __align__(16) __half g_Eh[N_ROWS * K_DIM];  // fp16(E * sqrt(log2e))
__device__ float        g_rowsum[4][N_ROWS];           // per-slot partials
__device__ int          g_lab[N_ROWS];
__device__ unsigned int g_count = 0;

// ---- smem byte offsets (fp16 tiles, 272B padded rows) ----
#define ROW_BYTES  272
#define TILE_BYTES (MT * ROW_BYTES)              // 34816
#define SM_A       0
#define SM_B       TILE_BYTES                    // 3 buffers
#define SM_LAB     (SM_B + 3 * TILE_BYTES)       // int[3][NT]
#define SM_RED     (SM_LAB + 3 * NT * 4)         // float[4][MT] = 512 floats
#define SM_TOTAL   (SM_RED + 4 * MT * 4)         // ~142.8 KB

__device__ __forceinline__ uint32_t smem_u32(const void* p) {
    uint32_t a;
    asm("{ .reg .u64 t; cvta.to.shared.u64 t, %1; cvt.u32.u64 %0, t; }" : "=r"(a) : "l"(p));
    return a;
}
__device__ __forceinline__ void cp_async16(uint32_t dst, const void* src) {
    asm volatile("cp.async.cg.shared.global [%0], [%1], 16;" :: "r"(dst), "l"(src) : "memory");
}
#define CP_COMMIT() asm volatile("cp.async.commit_group;" ::: "memory")
#define CP_WAIT1()  asm volatile("cp.async.wait_group 1;" ::: "memory")
#define CP_WAIT0()  asm volatile("cp.async.wait_group 0;" ::: "memory")

__device__ __forceinline__ void ldsm4(uint32_t& r0, uint32_t& r1, uint32_t& r2, uint32_t& r3,
                                      uint32_t addr) {
    asm volatile("ldmatrix.sync.aligned.m8n8.x4.shared.b16 {%0,%1,%2,%3}, [%4];"
                 : "=r"(r0), "=r"(r1), "=r"(r2), "=r"(r3) : "r"(addr));
}
__device__ __forceinline__ void mma_f16(float& c0, float& c1, float& c2, float& c3,
                                        uint32_t a0, uint32_t a1, uint32_t a2, uint32_t a3,
                                        uint32_t b0, uint32_t b1) {
    asm volatile(
        "mma.sync.aligned.m16n8k16.row.col.f32.f16.f16.f32 "
        "{%0,%1,%2,%3}, {%4,%5,%6,%7}, {%8,%9}, {%0,%1,%2,%3};"
        : "+f"(c0), "+f"(c1), "+f"(c2), "+f"(c3)
        : "r"(a0), "r"(a1), "r"(a2), "r"(a3), "r"(b0), "r"(b1));
}
__device__ __forceinline__ float ex2(float x) {
    float r;
    asm("ex2.approx.f32 %0, %1;" : "=f"(r) : "f"(x));
    return r;
}
// CTA owning flattened tile t under start(c) = floor(c*TOTAL_T/GRID)
__device__ __forceinline__ int ctaOf(int t) {
    return ((t + 1) * GRID - 1) / TOTAL_T;
}

// ---------------------------------------------------------------------------
// Stage: fp16-convert scaled embeddings, zero partial slots, fix labels.
// Labels: reference asks int64 but JAX w/o x64 emits int32 -> auto-detect.
// ---------------------------------------------------------------------------
__global__ void stage(const float* __restrict__ E, const int* __restrict__ lab32)
{
    const float4* E4 = (const float4*)E;
    int t = blockIdx.x * blockDim.x + threadIdx.x;   // 0..65535
    #pragma unroll
    for (int i = 0; i < 4; i++) {
        int idx = i * 65536 + t;                     // 262144 float4 total
        float4 v = E4[idx];
        __half2 h0 = __floats2half2_rn(v.x * SCALE_H, v.y * SCALE_H);
        __half2 h1 = __floats2half2_rn(v.z * SCALE_H, v.w * SCALE_H);
        uint2 u;
        u.x = *(const uint32_t*)&h0;
        u.y = *(const uint32_t*)&h1;
        reinterpret_cast<uint2*>(g_Eh)[idx] = u;
    }
    if (t < 4 * N_ROWS) ((float*)g_rowsum)[t] = 0.f;  // zero partial slots
    if (blockIdx.x == 0) {
        int local = 0;
        for (int i = threadIdx.x; i < N_ROWS / 2; i += blockDim.x)
            local |= lab32[2 * i + 1];
        int any_odd = __syncthreads_or(local);
        if (any_odd) {
            for (int i = threadIdx.x; i < N_ROWS; i += blockDim.x) g_lab[i] = lab32[i];
        } else {
            for (int i = threadIdx.x; i < N_ROWS; i += blockDim.x) g_lab[i] = lab32[2 * i];
        }
    }
}

// ---------------------------------------------------------------------------
// Main: balanced static schedule over 148 CTAs; fp16 warp-MMA with A in
// registers, 3-deep B pipeline, p-chunked fused ex2 epilogue, deterministic
// slotted partials + fused final reduction.
// ---------------------------------------------------------------------------
__global__ __launch_bounds__(NTHREADS, 1)
void npair_mma(float* __restrict__ out)
{
    extern __shared__ char smem[];
    const uint32_t sbase = smem_u32(smem);
    int*   labS = (int*)(smem + SM_LAB);      // [3][NT]
    float* red  = (float*)(smem + SM_RED);    // [4][MT]

    const int tid = threadIdx.x;
    const int wid = tid >> 5, lid = tid & 31;
    const int wm = wid >> 2;                  // 0..3 row 32-block
    const int wn = wid & 3;                   // 0..3 col 32-block
    const int qr = lid >> 2;                  // accum frag row 0..7
    const int qc = lid & 3;                   // accum frag colpair 0..3
    const int lq = lid >> 3;                  // ldmatrix quadrant 0..3
    const int lr = lid & 7;                   // ldmatrix row 0..7

    const int cta   = blockIdx.x;
    const int start = (int)(((long long)cta * TOTAL_T) / GRID);
    const int end   = (int)(((long long)(cta + 1) * TOTAL_T) / GRID);

    const uint32_t aBase = sbase + SM_A +
        (uint32_t)(wm * 32 + (lq & 1) * 8 + lr) * ROW_BYTES + (uint32_t)(lq >> 1) * 16;
    const uint32_t bBase0 = (uint32_t)(wn * 32 + (lq >> 1) * 8 + lr) * ROW_BYTES +
                            (uint32_t)(lq & 1) * 16;

    // ---- prefetch first two B tiles + labels ----
    #pragma unroll
    for (int j = 0; j < 2; j++) {
        int t = start + j;
        if (t < end) {
            const int ct = t & (CTILES - 1);
            uint32_t bdst = sbase + SM_B + (t % 3) * TILE_BYTES;
            #pragma unroll
            for (int u = 0; u < 4; u++) {
                int idx = u * NTHREADS + tid;
                int row = idx >> 4, c = idx & 15;
                cp_async16(bdst + row * ROW_BYTES + c * 16,
                           g_Eh + (size_t)(ct * NT + row) * K_DIM + c * 8);
            }
            CP_COMMIT();
            if (tid < NT) labS[(t % 3) * NT + tid] = g_lab[ct * NT + tid];
        }
    }

    uint32_t afr[8][2][4];
    int labr[4];
    float rowsum[4] = {0.f, 0.f, 0.f, 0.f};
    int cur_rb = -1;

    for (int t = start; t < end; t++) {
        const int rb  = t >> 6;
        const int buf = t % 3;

        if (rb != cur_rb) {
            // flush partials of previous rowblock
            if (cur_rb >= 0) {
                #pragma unroll
                for (int i = 0; i < 4; i++) {
                    rowsum[i] += __shfl_xor_sync(0xFFFFFFFF, rowsum[i], 1);
                    rowsum[i] += __shfl_xor_sync(0xFFFFFFFF, rowsum[i], 2);
                }
                __syncthreads();
                if (qc == 0) {
                    #pragma unroll
                    for (int rt = 0; rt < 2; rt++) {
                        red[wn * MT + wm * 32 + rt * 16 + qr]     = rowsum[rt * 2 + 0];
                        red[wn * MT + wm * 32 + rt * 16 + qr + 8] = rowsum[rt * 2 + 1];
                    }
                }
                __syncthreads();
                if (tid < MT) {
                    int slot = cta - ctaOf(cur_rb * CTILES);
                    g_rowsum[slot][cur_rb * MT + tid] =
                        red[tid] + red[MT + tid] + red[2 * MT + tid] + red[3 * MT + tid];
                }
                #pragma unroll
                for (int i = 0; i < 4; i++) rowsum[i] = 0.f;
            }
            // load A tile for rowblock rb and hoist fragments
            __syncthreads();
            #pragma unroll
            for (int u = 0; u < 4; u++) {
                int idx = u * NTHREADS + tid;
                int row = idx >> 4, c = idx & 15;
                uint4 v = *reinterpret_cast<const uint4*>(
                    (const char*)g_Eh + ((size_t)(rb * MT + row) * K_DIM + c * 8) * 2);
                *reinterpret_cast<uint4*>(smem + SM_A + row * ROW_BYTES + c * 16) = v;
            }
            __syncthreads();
            #pragma unroll
            for (int ks = 0; ks < 8; ks++)
                #pragma unroll
                for (int rt = 0; rt < 2; rt++)
                    ldsm4(afr[ks][rt][0], afr[ks][rt][1], afr[ks][rt][2], afr[ks][rt][3],
                          aBase + rt * 16 * ROW_BYTES + ks * 32);
            #pragma unroll
            for (int rt = 0; rt < 2; rt++) {
                labr[rt * 2 + 0] = g_lab[rb * MT + wm * 32 + rt * 16 + qr];
                labr[rt * 2 + 1] = g_lab[rb * MT + wm * 32 + rt * 16 + qr + 8];
            }
            cur_rb = rb;
        }

        if (t + 2 < end) CP_WAIT1(); else CP_WAIT0();
        __syncthreads();   // tile t visible to all; readers of tile t-1 done

        // prefetch tile t+2 into buffer (t+2)%3
        if (t + 2 < end) {
            const int t2 = t + 2;
            const int ct2 = t2 & (CTILES - 1);
            uint32_t bdst = sbase + SM_B + (t2 % 3) * TILE_BYTES;
            #pragma unroll
            for (int u = 0; u < 4; u++) {
                int idx = u * NTHREADS + tid;
                int row = idx >> 4, c = idx & 15;
                cp_async16(bdst + row * ROW_BYTES + c * 16,
                           g_Eh + (size_t)(ct2 * NT + row) * K_DIM + c * 8);
            }
            CP_COMMIT();
            if (tid < NT) labS[(t2 % 3) * NT + tid] = g_lab[ct2 * NT + tid];
        }

        // ---- compute tile t in two 16-column chunks, epilogue fused per chunk ----
        const uint32_t bBase = sbase + SM_B + buf * TILE_BYTES + bBase0;

        #pragma unroll
        for (int p = 0; p < 2; p++) {
            float cc[2][2][4];
            #pragma unroll
            for (int rt = 0; rt < 2; rt++)
                #pragma unroll
                for (int j = 0; j < 2; j++)
                    #pragma unroll
                    for (int q = 0; q < 4; q++) cc[rt][j][q] = 0.f;

            #pragma unroll
            for (int ks = 0; ks < 8; ks++) {
                uint32_t r0, r1, r2, r3;
                ldsm4(r0, r1, r2, r3, bBase + p * 16 * ROW_BYTES + ks * 32);
                #pragma unroll
                for (int rt = 0; rt < 2; rt++) {
                    mma_f16(cc[rt][0][0], cc[rt][0][1], cc[rt][0][2], cc[rt][0][3],
                            afr[ks][rt][0], afr[ks][rt][1], afr[ks][rt][2], afr[ks][rt][3],
                            r0, r1);
                    mma_f16(cc[rt][1][0], cc[rt][1][1], cc[rt][1][2], cc[rt][1][3],
                            afr[ks][rt][0], afr[ks][rt][1], afr[ks][rt][2], afr[ks][rt][3],
                            r2, r3);
                }
            }

            // epilogue for columns [wn*32 + p*16, +16)
            #pragma unroll
            for (int j = 0; j < 2; j++) {
                int n0 = wn * 32 + (2 * p + j) * 8 + 2 * qc;
                int lc0 = labS[buf * NT + n0];
                int lc1 = labS[buf * NT + n0 + 1];
                #pragma unroll
                for (int rt = 0; rt < 2; rt++) {
                    float u0 = cc[rt][j][0] - M_L2;
                    float u1 = cc[rt][j][1] - M_L2;
                    float u2 = cc[rt][j][2] - M_L2;
                    float u3 = cc[rt][j][3] - M_L2;
                    uint32_t f0 = (labr[rt * 2 + 0] == lc0) ? 0x80000000u : 0u;
                    uint32_t f1 = (labr[rt * 2 + 0] == lc1) ? 0x80000000u : 0u;
                    uint32_t f2 = (labr[rt * 2 + 1] == lc0) ? 0x80000000u : 0u;
                    uint32_t f3 = (labr[rt * 2 + 1] == lc1) ? 0x80000000u : 0u;
                    rowsum[rt * 2 + 0] += ex2(__uint_as_float(__float_as_uint(u0) ^ f0))
                                        + ex2(__uint_as_float(__float_as_uint(u1) ^ f1));
                    rowsum[rt * 2 + 1] += ex2(__uint_as_float(__float_as_uint(u2) ^ f2))
                                        + ex2(__uint_as_float(__float_as_uint(u3) ^ f3));
                }
            }
        }
    }

    // ---- flush last rowblock ----
    #pragma unroll
    for (int i = 0; i < 4; i++) {
        rowsum[i] += __shfl_xor_sync(0xFFFFFFFF, rowsum[i], 1);
        rowsum[i] += __shfl_xor_sync(0xFFFFFFFF, rowsum[i], 2);
    }
    __syncthreads();
    if (qc == 0) {
        #pragma unroll
        for (int rt = 0; rt < 2; rt++) {
            red[wn * MT + wm * 32 + rt * 16 + qr]     = rowsum[rt * 2 + 0];
            red[wn * MT + wm * 32 + rt * 16 + qr + 8] = rowsum[rt * 2 + 1];
        }
    }
    __syncthreads();
    if (tid < MT) {
        int slot = cta - ctaOf(cur_rb * CTILES);
        g_rowsum[slot][cur_rb * MT + tid] =
            red[tid] + red[MT + tid] + red[2 * MT + tid] + red[3 * MT + tid];
    }

    // ---- fused final reduction: last-arriving CTA computes the loss ----
    __shared__ int lastFlag;
    if (tid == 0) {
        __threadfence();
        unsigned int old = atomicAdd(&g_count, 1u);
        lastFlag = (old == (unsigned)(gridDim.x - 1));
    }
    __syncthreads();
    if (lastFlag) {
        __threadfence();
        float s = 0.f;
        #pragma unroll
        for (int i = 0; i < N_ROWS / NTHREADS; i++) {
            int r = i * NTHREADS + tid;      // fixed order per thread
            s += logf(g_rowsum[0][r] + g_rowsum[1][r] + g_rowsum[2][r] + g_rowsum[3][r]);
        }
        float* redf = (float*)(smem + SM_RED);
        redf[tid] = s;
        __syncthreads();
        for (int st = NTHREADS / 2; st > 0; st >>= 1) {
            if (tid < st) redf[tid] += redf[tid + st];
            __syncthreads();
        }
        if (tid == 0) {
            out[0] = redf[0] / (float)N_ROWS;
            g_count = 0;                     // reset for next (graph) launch
        }
    }
}

extern "C" void kernel_launch(void* const* d_in, const int* in_sizes, int n_in,
                              void* d_out, int out_size)
{
    const float* E   = (const float*)d_in[0];
    const int*   lab = (const int*)d_in[1];
    float*       out = (float*)d_out;

    cudaFuncSetAttribute(npair_mma, cudaFuncAttributeMaxDynamicSharedMemorySize, SM_TOTAL);

    stage<<<256, 256>>>(E, lab);
    npair_mma<<<GRID, NTHREADS, SM_TOTAL>>>(out);
}

// round 12
// speedup vs baseline: 15.5663x; 1.0004x over previous
#include <cuda_runtime.h>
#include <cuda_fp16.h>
#include <cstdint>
#include <math.h>

#define N_ROWS   8192
#define K_DIM    128
#define MT       128
#define NT       128
#define NTHREADS 512              // 16 warps
#define GRID     148
#define RBLOCKS  (N_ROWS / MT)    // 64
#define CTILES   (N_ROWS / NT)    // 64
#define TOTAL_T  (RBLOCKS * CTILES)  // 4096
#define LOG2E    1.4426950408889634f
#define SCALE_H  1.2011224087864498f   // sqrt(log2e): GEMM yields sim*log2e
#define M_L2     (0.1f * LOG2E)

// ---- static device scratch ----
__device__ __align__(16) __half g_Eh[N_ROWS * K_DIM];  // fp16(E * sqrt(log2e))
__device__ float        g_rowsum[4][N_ROWS];           // per-slot partials
__device__ int          g_lab[N_ROWS];
__device__ unsigned int g_count = 0;

// ---- smem byte offsets (fp16 tiles, 272B padded rows) ----
#define ROW_BYTES  272
#define TILE_BYTES (MT * ROW_BYTES)              // 34816
#define SM_A       0
#define SM_B       TILE_BYTES                    // 3 buffers
#define SM_LAB     (SM_B + 3 * TILE_BYTES)       // int[3][NT]
#define SM_RED     (SM_LAB + 3 * NT * 4)         // float[4][MT] = 512 floats
#define SM_TOTAL   (SM_RED + 4 * MT * 4)         // ~142.8 KB

__device__ __forceinline__ uint32_t smem_u32(const void* p) {
    uint32_t a;
    asm("{ .reg .u64 t; cvta.to.shared.u64 t, %1; cvt.u32.u64 %0, t; }" : "=r"(a) : "l"(p));
    return a;
}
__device__ __forceinline__ void cp_async16(uint32_t dst, const void* src) {
    asm volatile("cp.async.cg.shared.global [%0], [%1], 16;" :: "r"(dst), "l"(src) : "memory");
}
#define CP_COMMIT() asm volatile("cp.async.commit_group;" ::: "memory")
#define CP_WAIT1()  asm volatile("cp.async.wait_group 1;" ::: "memory")
#define CP_WAIT0()  asm volatile("cp.async.wait_group 0;" ::: "memory")

__device__ __forceinline__ void ldsm4(uint32_t& r0, uint32_t& r1, uint32_t& r2, uint32_t& r3,
                                      uint32_t addr) {
    asm volatile("ldmatrix.sync.aligned.m8n8.x4.shared.b16 {%0,%1,%2,%3}, [%4];"
                 : "=r"(r0), "=r"(r1), "=r"(r2), "=r"(r3) : "r"(addr));
}
__device__ __forceinline__ void ldsm2(uint32_t& r0, uint32_t& r1, uint32_t addr) {
    asm volatile("ldmatrix.sync.aligned.m8n8.x2.shared.b16 {%0,%1}, [%2];"
                 : "=r"(r0), "=r"(r1) : "r"(addr));
}
__device__ __forceinline__ void mma_f16(float& c0, float& c1, float& c2, float& c3,
                                        uint32_t a0, uint32_t a1, uint32_t a2, uint32_t a3,
                                        uint32_t b0, uint32_t b1) {
    asm volatile(
        "mma.sync.aligned.m16n8k16.row.col.f32.f16.f16.f32 "
        "{%0,%1,%2,%3}, {%4,%5,%6,%7}, {%8,%9}, {%0,%1,%2,%3};"
        : "+f"(c0), "+f"(c1), "+f"(c2), "+f"(c3)
        : "r"(a0), "r"(a1), "r"(a2), "r"(a3), "r"(b0), "r"(b1));
}
__device__ __forceinline__ float ex2(float x) {
    float r;
    asm("ex2.approx.f32 %0, %1;" : "=f"(r) : "f"(x));
    return r;
}
// CTA owning flattened tile t under start(c) = floor(c*TOTAL_T/GRID)
__device__ __forceinline__ int ctaOf(int t) {
    return ((t + 1) * GRID - 1) / TOTAL_T;
}

// ---------------------------------------------------------------------------
// Stage: fp16-convert scaled embeddings, zero partial slots, fix labels.
// Labels: reference asks int64 but JAX w/o x64 emits int32 -> auto-detect.
// ---------------------------------------------------------------------------
__global__ void stage(const float* __restrict__ E, const int* __restrict__ lab32)
{
    const float4* E4 = (const float4*)E;
    int t = blockIdx.x * blockDim.x + threadIdx.x;   // 0..65535
    #pragma unroll
    for (int i = 0; i < 4; i++) {
        int idx = i * 65536 + t;                     // 262144 float4 total
        float4 v = E4[idx];
        __half2 h0 = __floats2half2_rn(v.x * SCALE_H, v.y * SCALE_H);
        __half2 h1 = __floats2half2_rn(v.z * SCALE_H, v.w * SCALE_H);
        uint2 u;
        u.x = *(const uint32_t*)&h0;
        u.y = *(const uint32_t*)&h1;
        reinterpret_cast<uint2*>(g_Eh)[idx] = u;
    }
    if (t < 4 * N_ROWS) ((float*)g_rowsum)[t] = 0.f;  // zero partial slots
    if (blockIdx.x == 0) {
        int local = 0;
        for (int i = threadIdx.x; i < N_ROWS / 2; i += blockDim.x)
            local |= lab32[2 * i + 1];
        int any_odd = __syncthreads_or(local);
        if (any_odd) {
            for (int i = threadIdx.x; i < N_ROWS; i += blockDim.x) g_lab[i] = lab32[i];
        } else {
            for (int i = threadIdx.x; i < N_ROWS; i += blockDim.x) g_lab[i] = lab32[2 * i];
        }
    }
}

// ---------------------------------------------------------------------------
// Main: balanced static schedule over 148 CTAs; fp16 warp-MMA with A in
// registers, 3-deep B pipeline, software-pipelined epilogue (epi of chunk
// c-1 overlaps MMA of chunk c), deterministic slotted partials + fused
// final reduction.
// ---------------------------------------------------------------------------
__global__ __launch_bounds__(NTHREADS, 1)
void npair_mma(float* __restrict__ out)
{
    extern __shared__ char smem[];
    const uint32_t sbase = smem_u32(smem);
    int*   labS = (int*)(smem + SM_LAB);      // [3][NT]
    float* red  = (float*)(smem + SM_RED);    // [4][MT]

    const int tid = threadIdx.x;
    const int wid = tid >> 5, lid = tid & 31;
    const int wm = wid >> 2;                  // 0..3 row 32-block
    const int wn = wid & 3;                   // 0..3 col 32-block
    const int qr = lid >> 2;                  // accum frag row 0..7
    const int qc = lid & 3;                   // accum frag colpair 0..3
    const int lq = lid >> 3;                  // ldmatrix quadrant 0..3
    const int lr = lid & 7;                   // ldmatrix row 0..7

    const int cta   = blockIdx.x;
    const int start = (int)(((long long)cta * TOTAL_T) / GRID);
    const int end   = (int)(((long long)(cta + 1) * TOTAL_T) / GRID);

    const uint32_t aBase = sbase + SM_A +
        (uint32_t)(wm * 32 + (lq & 1) * 8 + lr) * ROW_BYTES + (uint32_t)(lq >> 1) * 16;
    // ldsm2 per-lane base: lanes 0-7 matrix0 (k0-7), 8-15 matrix1 (k8-15);
    // lanes 16-31 replicate (addresses unused but kept valid)
    const uint32_t bBase0 = (uint32_t)(wn * 32 + lr) * ROW_BYTES +
                            (uint32_t)((lid >> 3) & 1) * 16;

    // ---- prefetch first two B tiles + labels ----
    #pragma unroll
    for (int j = 0; j < 2; j++) {
        int t = start + j;
        if (t < end) {
            const int ct = t & (CTILES - 1);
            uint32_t bdst = sbase + SM_B + (t % 3) * TILE_BYTES;
            #pragma unroll
            for (int u = 0; u < 4; u++) {
                int idx = u * NTHREADS + tid;
                int row = idx >> 4, c = idx & 15;
                cp_async16(bdst + row * ROW_BYTES + c * 16,
                           g_Eh + (size_t)(ct * NT + row) * K_DIM + c * 8);
            }
            CP_COMMIT();
            if (tid < NT) labS[(t % 3) * NT + tid] = g_lab[ct * NT + tid];
        }
    }

    uint32_t afr[8][2][4];
    int labr[4];
    float rowsum[4] = {0.f, 0.f, 0.f, 0.f};
    int cur_rb = -1;

    for (int t = start; t < end; t++) {
        const int rb  = t >> 6;
        const int buf = t % 3;

        if (rb != cur_rb) {
            // flush partials of previous rowblock
            if (cur_rb >= 0) {
                #pragma unroll
                for (int i = 0; i < 4; i++) {
                    rowsum[i] += __shfl_xor_sync(0xFFFFFFFF, rowsum[i], 1);
                    rowsum[i] += __shfl_xor_sync(0xFFFFFFFF, rowsum[i], 2);
                }
                __syncthreads();
                if (qc == 0) {
                    #pragma unroll
                    for (int rt = 0; rt < 2; rt++) {
                        red[wn * MT + wm * 32 + rt * 16 + qr]     = rowsum[rt * 2 + 0];
                        red[wn * MT + wm * 32 + rt * 16 + qr + 8] = rowsum[rt * 2 + 1];
                    }
                }
                __syncthreads();
                if (tid < MT) {
                    int slot = cta - ctaOf(cur_rb * CTILES);
                    g_rowsum[slot][cur_rb * MT + tid] =
                        red[tid] + red[MT + tid] + red[2 * MT + tid] + red[3 * MT + tid];
                }
                #pragma unroll
                for (int i = 0; i < 4; i++) rowsum[i] = 0.f;
            }
            // load A tile for rowblock rb and hoist fragments
            __syncthreads();
            #pragma unroll
            for (int u = 0; u < 4; u++) {
                int idx = u * NTHREADS + tid;
                int row = idx >> 4, c = idx & 15;
                uint4 v = *reinterpret_cast<const uint4*>(
                    (const char*)g_Eh + ((size_t)(rb * MT + row) * K_DIM + c * 8) * 2);
                *reinterpret_cast<uint4*>(smem + SM_A + row * ROW_BYTES + c * 16) = v;
            }
            __syncthreads();
            #pragma unroll
            for (int ks = 0; ks < 8; ks++)
                #pragma unroll
                for (int rt = 0; rt < 2; rt++)
                    ldsm4(afr[ks][rt][0], afr[ks][rt][1], afr[ks][rt][2], afr[ks][rt][3],
                          aBase + rt * 16 * ROW_BYTES + ks * 32);
            #pragma unroll
            for (int rt = 0; rt < 2; rt++) {
                labr[rt * 2 + 0] = g_lab[rb * MT + wm * 32 + rt * 16 + qr];
                labr[rt * 2 + 1] = g_lab[rb * MT + wm * 32 + rt * 16 + qr + 8];
            }
            cur_rb = rb;
        }

        if (t + 2 < end) CP_WAIT1(); else CP_WAIT0();
        __syncthreads();   // tile t visible to all; readers of tile t-1 done

        // prefetch tile t+2 into buffer (t+2)%3
        if (t + 2 < end) {
            const int t2 = t + 2;
            const int ct2 = t2 & (CTILES - 1);
            uint32_t bdst = sbase + SM_B + (t2 % 3) * TILE_BYTES;
            #pragma unroll
            for (int u = 0; u < 4; u++) {
                int idx = u * NTHREADS + tid;
                int row = idx >> 4, c = idx & 15;
                cp_async16(bdst + row * ROW_BYTES + c * 16,
                           g_Eh + (size_t)(ct2 * NT + row) * K_DIM + c * 8);
            }
            CP_COMMIT();
            if (tid < NT) labS[(t2 % 3) * NT + tid] = g_lab[ct2 * NT + tid];
        }

        // ---- tile t: 4 chunks of 8 columns, pipelined MMA(c) || epi(c-1) ----
        const uint32_t bB = sbase + SM_B + buf * TILE_BYTES + bBase0;
        const int labBase = buf * NT + wn * 32 + 2 * qc;

        float ccp[8];
        int lcp0 = 0, lcp1 = 0;

        #pragma unroll
        for (int c = 0; c < 5; c++) {
            float cc[8];
            if (c < 4) {
                #pragma unroll
                for (int q = 0; q < 8; q++) cc[q] = 0.f;
                #pragma unroll
                for (int ks = 0; ks < 8; ks++) {
                    uint32_t b0, b1;
                    ldsm2(b0, b1, bB + c * 8 * ROW_BYTES + ks * 32);
                    mma_f16(cc[0], cc[1], cc[2], cc[3],
                            afr[ks][0][0], afr[ks][0][1], afr[ks][0][2], afr[ks][0][3],
                            b0, b1);
                    mma_f16(cc[4], cc[5], cc[6], cc[7],
                            afr[ks][1][0], afr[ks][1][1], afr[ks][1][2], afr[ks][1][3],
                            b0, b1);
                }
            }
            if (c > 0) {
                // epilogue for chunk c-1 (accumulators ccp, labels lcp*)
                #pragma unroll
                for (int rt = 0; rt < 2; rt++) {
                    float u0 = ccp[rt * 4 + 0] - M_L2;
                    float u1 = ccp[rt * 4 + 1] - M_L2;
                    float u2 = ccp[rt * 4 + 2] - M_L2;
                    float u3 = ccp[rt * 4 + 3] - M_L2;
                    uint32_t f0 = (labr[rt * 2 + 0] == lcp0) ? 0x80000000u : 0u;
                    uint32_t f1 = (labr[rt * 2 + 0] == lcp1) ? 0x80000000u : 0u;
                    uint32_t f2 = (labr[rt * 2 + 1] == lcp0) ? 0x80000000u : 0u;
                    uint32_t f3 = (labr[rt * 2 + 1] == lcp1) ? 0x80000000u : 0u;
                    rowsum[rt * 2 + 0] += ex2(__uint_as_float(__float_as_uint(u0) ^ f0))
                                        + ex2(__uint_as_float(__float_as_uint(u1) ^ f1));
                    rowsum[rt * 2 + 1] += ex2(__uint_as_float(__float_as_uint(u2) ^ f2))
                                        + ex2(__uint_as_float(__float_as_uint(u3) ^ f3));
                }
            }
            if (c < 4) {
                #pragma unroll
                for (int q = 0; q < 8; q++) ccp[q] = cc[q];
                lcp0 = labS[labBase + c * 8];
                lcp1 = labS[labBase + c * 8 + 1];
            }
        }
    }

    // ---- flush last rowblock ----
    #pragma unroll
    for (int i = 0; i < 4; i++) {
        rowsum[i] += __shfl_xor_sync(0xFFFFFFFF, rowsum[i], 1);
        rowsum[i] += __shfl_xor_sync(0xFFFFFFFF, rowsum[i], 2);
    }
    __syncthreads();
    if (qc == 0) {
        #pragma unroll
        for (int rt = 0; rt < 2; rt++) {
            red[wn * MT + wm * 32 + rt * 16 + qr]     = rowsum[rt * 2 + 0];
            red[wn * MT + wm * 32 + rt * 16 + qr + 8] = rowsum[rt * 2 + 1];
        }
    }
    __syncthreads();
    if (tid < MT) {
        int slot = cta - ctaOf(cur_rb * CTILES);
        g_rowsum[slot][cur_rb * MT + tid] =
            red[tid] + red[MT + tid] + red[2 * MT + tid] + red[3 * MT + tid];
    }

    // ---- fused final reduction: last-arriving CTA computes the loss ----
    __shared__ int lastFlag;
    if (tid == 0) {
        __threadfence();
        unsigned int old = atomicAdd(&g_count, 1u);
        lastFlag = (old == (unsigned)(gridDim.x - 1));
    }
    __syncthreads();
    if (lastFlag) {
        __threadfence();
        float s = 0.f;
        #pragma unroll
        for (int i = 0; i < N_ROWS / NTHREADS; i++) {
            int r = i * NTHREADS + tid;      // fixed order per thread
            s += logf(g_rowsum[0][r] + g_rowsum[1][r] + g_rowsum[2][r] + g_rowsum[3][r]);
        }
        float* redf = (float*)(smem + SM_RED);
        redf[tid] = s;
        __syncthreads();
        for (int st = NTHREADS / 2; st > 0; st >>= 1) {
            if (tid < st) redf[tid] += redf[tid + st];
            __syncthreads();
        }
        if (tid == 0) {
            out[0] = redf[0] / (float)N_ROWS;
            g_count = 0;                     // reset for next (graph) launch
        }
    }
}

extern "C" void kernel_launch(void* const* d_in, const int* in_sizes, int n_in,
                              void* d_out, int out_size)
{
    const float* E   = (const float*)d_in[0];
    const int*   lab = (const int*)d_in[1];
    float*       out = (float*)d_out;

    cudaFuncSetAttribute(npair_mma, cudaFuncAttributeMaxDynamicSharedMemorySize, SM_TOTAL);

    stage<<<256, 256>>>(E, lab);
    npair_mma<<<GRID, NTHREADS, SM_TOTAL>>>(out);
}

// round 14
// speedup vs baseline: 16.5031x; 1.0602x over previous
#include <cuda_runtime.h>
#include <cuda_fp16.h>
#include <cstdint>
#include <math.h>

#define N_ROWS   8192
#define K_DIM    128
#define MT       128
#define NT       128
#define NTHREADS 256              // 8 warps
#define GRID     296              // 2 CTAs per SM
#define NSLOT    6
#define RBLOCKS  (N_ROWS / MT)    // 64
#define CTILES   (N_ROWS / NT)    // 64
#define TOTAL_T  (RBLOCKS * CTILES)  // 4096
#define LOG2E    1.4426950408889634f
#define SCALE_H  1.2011224087864498f   // sqrt(log2e): GEMM yields sim*log2e
#define M_L2     (0.1f * LOG2E)

// ---- static device scratch ----
__device__ __align__(16) __half g_Eh[N_ROWS * K_DIM];  // fp16(E * sqrt(log2e))
__device__ float        g_rowsum[NSLOT][N_ROWS];       // per-slot partials
__device__ int          g_lab[N_ROWS];
__device__ unsigned int g_count = 0;

// ---- smem byte offsets (fp16 tiles, 272B padded rows) ----
#define ROW_BYTES  272
#define TILE_BYTES (MT * ROW_BYTES)              // 34816
#define SM_A       0
#define SM_B       TILE_BYTES                    // 2 buffers
#define SM_LAB     (SM_B + 2 * TILE_BYTES)       // int[2][NT]
#define SM_RED     (SM_LAB + 2 * NT * 4)         // float[2][MT] (also final redf)
#define SM_TOTAL   (SM_RED + 2 * MT * 4)         // 105,472 B -> 2 CTAs/SM

__device__ __forceinline__ uint32_t smem_u32(const void* p) {
    uint32_t a;
    asm("{ .reg .u64 t; cvta.to.shared.u64 t, %1; cvt.u32.u64 %0, t; }" : "=r"(a) : "l"(p));
    return a;
}
__device__ __forceinline__ void cp_async16(uint32_t dst, const void* src) {
    asm volatile("cp.async.cg.shared.global [%0], [%1], 16;" :: "r"(dst), "l"(src) : "memory");
}
#define CP_COMMIT() asm volatile("cp.async.commit_group;" ::: "memory")
#define CP_WAIT0()  asm volatile("cp.async.wait_group 0;" ::: "memory")

__device__ __forceinline__ void ldsm4(uint32_t& r0, uint32_t& r1, uint32_t& r2, uint32_t& r3,
                                      uint32_t addr) {
    asm volatile("ldmatrix.sync.aligned.m8n8.x4.shared.b16 {%0,%1,%2,%3}, [%4];"
                 : "=r"(r0), "=r"(r1), "=r"(r2), "=r"(r3) : "r"(addr));
}
__device__ __forceinline__ void ldsm2(uint32_t& r0, uint32_t& r1, uint32_t addr) {
    asm volatile("ldmatrix.sync.aligned.m8n8.x2.shared.b16 {%0,%1}, [%2];"
                 : "=r"(r0), "=r"(r1) : "r"(addr));
}
__device__ __forceinline__ void mma_f16(float& c0, float& c1, float& c2, float& c3,
                                        uint32_t a0, uint32_t a1, uint32_t a2, uint32_t a3,
                                        uint32_t b0, uint32_t b1) {
    asm volatile(
        "mma.sync.aligned.m16n8k16.row.col.f32.f16.f16.f32 "
        "{%0,%1,%2,%3}, {%4,%5,%6,%7}, {%8,%9}, {%0,%1,%2,%3};"
        : "+f"(c0), "+f"(c1), "+f"(c2), "+f"(c3)
        : "r"(a0), "r"(a1), "r"(a2), "r"(a3), "r"(b0), "r"(b1));
}
__device__ __forceinline__ float ex2(float x) {
    float r;
    asm("ex2.approx.f32 %0, %1;" : "=f"(r) : "f"(x));
    return r;
}
__device__ __forceinline__ int ctaOf(int t) {
    return (int)(((long long)(t + 1) * GRID - 1) / TOTAL_T);
}

// ---------------------------------------------------------------------------
// Stage: fp16-convert scaled embeddings, zero partial slots, fix labels.
// Labels: reference asks int64 but JAX w/o x64 emits int32 -> auto-detect.
// ---------------------------------------------------------------------------
__global__ void stage(const float* __restrict__ E, const int* __restrict__ lab32)
{
    const float4* E4 = (const float4*)E;
    int t = blockIdx.x * blockDim.x + threadIdx.x;   // 0..65535
    #pragma unroll
    for (int i = 0; i < 4; i++) {
        int idx = i * 65536 + t;                     // 262144 float4 total
        float4 v = E4[idx];
        __half2 h0 = __floats2half2_rn(v.x * SCALE_H, v.y * SCALE_H);
        __half2 h1 = __floats2half2_rn(v.z * SCALE_H, v.w * SCALE_H);
        uint2 u;
        u.x = *(const uint32_t*)&h0;
        u.y = *(const uint32_t*)&h1;
        reinterpret_cast<uint2*>(g_Eh)[idx] = u;
    }
    if (t < NSLOT * N_ROWS) ((float*)g_rowsum)[t] = 0.f;
    if (blockIdx.x == 0) {
        int local = 0;
        for (int i = threadIdx.x; i < N_ROWS / 2; i += blockDim.x)
            local |= lab32[2 * i + 1];
        int any_odd = __syncthreads_or(local);
        if (any_odd) {
            for (int i = threadIdx.x; i < N_ROWS; i += blockDim.x) g_lab[i] = lab32[i];
        } else {
            for (int i = threadIdx.x; i < N_ROWS; i += blockDim.x) g_lab[i] = lab32[2 * i];
        }
    }
}

// ---------------------------------------------------------------------------
// Main: 296 CTAs (2/SM) x 8 warps; warp tile 32x64 in 8-col chunks.
// A fragments register-resident per rowblock; 2-deep B pipeline with one
// barrier per tile (prefetch issued after the barrier). Fused ex2 epilogue
// with label sign applied BEFORE exponentiation. Deterministic slotted
// partials + fused final reduction.
// ---------------------------------------------------------------------------
__global__ __launch_bounds__(NTHREADS, 2)
void npair_mma(float* __restrict__ out)
{
    extern __shared__ char smem[];
    const uint32_t sbase = smem_u32(smem);
    int*   labS = (int*)(smem + SM_LAB);      // [2][NT]
    float* red  = (float*)(smem + SM_RED);    // [2][MT]

    const int tid = threadIdx.x;
    const int wid = tid >> 5, lid = tid & 31;
    const int wm = wid >> 1;                  // 0..3 row 32-block
    const int wn = wid & 1;                   // 0..1 col 64-block
    const int qr = lid >> 2;                  // accum frag row 0..7
    const int qc = lid & 3;                   // accum frag colpair 0..3
    const int lq = lid >> 3;                  // ldmatrix quadrant 0..3
    const int lr = lid & 7;                   // ldmatrix row 0..7

    const int cta   = blockIdx.x;
    const int start = (int)(((long long)cta * TOTAL_T) / GRID);
    const int end   = (int)(((long long)(cta + 1) * TOTAL_T) / GRID);

    const uint32_t aBase = sbase + SM_A +
        (uint32_t)(wm * 32 + (lq & 1) * 8 + lr) * ROW_BYTES + (uint32_t)(lq >> 1) * 16;
    // ldsm2 lanes 0-7: rows (k0-7); lanes 8-15: +16B (k8-15); 16-31 unused
    const uint32_t bBase0 = (uint32_t)(wn * 64 + lr) * ROW_BYTES +
                            (uint32_t)((lid >> 3) & 1) * 16;

    // ---- prefetch first B tile + labels ----
    {
        const int ct = start & (CTILES - 1);
        uint32_t bdst = sbase + SM_B + (start & 1) * TILE_BYTES;
        #pragma unroll
        for (int u = 0; u < 8; u++) {
            int idx = u * NTHREADS + tid;        // 2048 16B chunks
            int row = idx >> 4, c = idx & 15;
            cp_async16(bdst + row * ROW_BYTES + c * 16,
                       g_Eh + (size_t)(ct * NT + row) * K_DIM + c * 8);
        }
        CP_COMMIT();
        if (tid < NT) labS[(start & 1) * NT + tid] = g_lab[ct * NT + tid];
    }

    uint32_t afr[8][2][4];
    int labr[4];
    float rowsum[4] = {0.f, 0.f, 0.f, 0.f};
    int cur_rb = -1;

    for (int t = start; t < end; t++) {
        const int rb  = t >> 6;
        const int buf = t & 1;

        if (rb != cur_rb) {
            if (cur_rb >= 0) {   // flush partials of previous rowblock
                #pragma unroll
                for (int i = 0; i < 4; i++) {
                    rowsum[i] += __shfl_xor_sync(0xFFFFFFFF, rowsum[i], 1);
                    rowsum[i] += __shfl_xor_sync(0xFFFFFFFF, rowsum[i], 2);
                }
                __syncthreads();
                if (qc == 0) {
                    #pragma unroll
                    for (int i = 0; i < 4; i++)
                        red[wn * MT + wm * 32 + i * 8 + qr] = rowsum[i];
                }
                __syncthreads();
                if (tid < MT) {
                    int slot = cta - ctaOf(cur_rb * CTILES);
                    g_rowsum[slot][cur_rb * MT + tid] = red[tid] + red[MT + tid];
                }
                #pragma unroll
                for (int i = 0; i < 4; i++) rowsum[i] = 0.f;
            }
            __syncthreads();
            #pragma unroll
            for (int u = 0; u < 8; u++) {        // load A tile
                int idx = u * NTHREADS + tid;
                int row = idx >> 4, c = idx & 15;
                uint4 v = *reinterpret_cast<const uint4*>(
                    (const char*)g_Eh + ((size_t)(rb * MT + row) * K_DIM + c * 8) * 2);
                *reinterpret_cast<uint4*>(smem + SM_A + row * ROW_BYTES + c * 16) = v;
            }
            __syncthreads();
            #pragma unroll
            for (int ks = 0; ks < 8; ks++)
                #pragma unroll
                for (int rt = 0; rt < 2; rt++)
                    ldsm4(afr[ks][rt][0], afr[ks][rt][1], afr[ks][rt][2], afr[ks][rt][3],
                          aBase + rt * 16 * ROW_BYTES + ks * 32);
            #pragma unroll
            for (int i = 0; i < 4; i++)
                labr[i] = g_lab[rb * MT + wm * 32 + i * 8 + qr];
            cur_rb = rb;
        }

        CP_WAIT0();
        __syncthreads();   // tile t visible; everyone done with tile t-1's buffer

        // prefetch tile t+1 into the other buffer (free now)
        if (t + 1 < end) {
            const int ct2 = (t + 1) & (CTILES - 1);
            uint32_t bdst = sbase + SM_B + ((t + 1) & 1) * TILE_BYTES;
            #pragma unroll
            for (int u = 0; u < 8; u++) {
                int idx = u * NTHREADS + tid;
                int row = idx >> 4, c = idx & 15;
                cp_async16(bdst + row * ROW_BYTES + c * 16,
                           g_Eh + (size_t)(ct2 * NT + row) * K_DIM + c * 8);
            }
            CP_COMMIT();
            if (tid < NT) labS[((t + 1) & 1) * NT + tid] = g_lab[ct2 * NT + tid];
        }

        // ---- tile t: 8 chunks of 8 columns (warp cols = wn*64..+63) ----
        const uint32_t bB = sbase + SM_B + buf * TILE_BYTES + bBase0;
        const int labBase = buf * NT + wn * 64 + 2 * qc;

        #pragma unroll
        for (int c = 0; c < 8; c++) {
            float acc[8];
            #pragma unroll
            for (int q = 0; q < 8; q++) acc[q] = 0.f;
            #pragma unroll
            for (int ks = 0; ks < 8; ks++) {
                uint32_t b0, b1;
                ldsm2(b0, b1, bB + c * 8 * ROW_BYTES + ks * 32);
                mma_f16(acc[0], acc[1], acc[2], acc[3],
                        afr[ks][0][0], afr[ks][0][1], afr[ks][0][2], afr[ks][0][3],
                        b0, b1);
                mma_f16(acc[4], acc[5], acc[6], acc[7],
                        afr[ks][1][0], afr[ks][1][1], afr[ks][1][2], afr[ks][1][3],
                        b0, b1);
            }
            const int lc0 = labS[labBase + c * 8];
            const int lc1 = labS[labBase + c * 8 + 1];
            #pragma unroll
            for (int rt = 0; rt < 2; rt++) {
                float u0 = acc[rt * 4 + 0] - M_L2;
                float u1 = acc[rt * 4 + 1] - M_L2;
                float u2 = acc[rt * 4 + 2] - M_L2;
                float u3 = acc[rt * 4 + 3] - M_L2;
                uint32_t f0 = (labr[rt * 2 + 0] == lc0) ? 0x80000000u : 0u;
                uint32_t f1 = (labr[rt * 2 + 0] == lc1) ? 0x80000000u : 0u;
                uint32_t f2 = (labr[rt * 2 + 1] == lc0) ? 0x80000000u : 0u;
                uint32_t f3 = (labr[rt * 2 + 1] == lc1) ? 0x80000000u : 0u;
                rowsum[rt * 2 + 0] += ex2(__uint_as_float(__float_as_uint(u0) ^ f0))
                                    + ex2(__uint_as_float(__float_as_uint(u1) ^ f1));
                rowsum[rt * 2 + 1] += ex2(__uint_as_float(__float_as_uint(u2) ^ f2))
                                    + ex2(__uint_as_float(__float_as_uint(u3) ^ f3));
            }
        }
    }

    // ---- flush last rowblock ----
    #pragma unroll
    for (int i = 0; i < 4; i++) {
        rowsum[i] += __shfl_xor_sync(0xFFFFFFFF, rowsum[i], 1);
        rowsum[i] += __shfl_xor_sync(0xFFFFFFFF, rowsum[i], 2);
    }
    __syncthreads();
    if (qc == 0) {
        #pragma unroll
        for (int i = 0; i < 4; i++)
            red[wn * MT + wm * 32 + i * 8 + qr] = rowsum[i];
    }
    __syncthreads();
    if (tid < MT) {
        int slot = cta - ctaOf(cur_rb * CTILES);
        g_rowsum[slot][cur_rb * MT + tid] = red[tid] + red[MT + tid];
    }

    // ---- fused final reduction: last-arriving CTA computes the loss ----
    __shared__ int lastFlag;
    if (tid == 0) {
        __threadfence();
        unsigned int old = atomicAdd(&g_count, 1u);
        lastFlag = (old == (unsigned)(gridDim.x - 1));
    }
    __syncthreads();
    if (lastFlag) {
        __threadfence();
        float s = 0.f;
        #pragma unroll
        for (int i = 0; i < N_ROWS / NTHREADS; i++) {
            int r = i * NTHREADS + tid;      // fixed order per thread
            float S = g_rowsum[0][r] + g_rowsum[1][r] + g_rowsum[2][r]
                    + g_rowsum[3][r] + g_rowsum[4][r] + g_rowsum[5][r];
            s += logf(S);
        }
        float* redf = (float*)(smem + SM_RED);
        redf[tid] = s;
        __syncthreads();
        for (int st = NTHREADS / 2; st > 0; st >>= 1) {
            if (tid < st) redf[tid] += redf[tid + st];
            __syncthreads();
        }
        if (tid == 0) {
            out[0] = redf[0] / (float)N_ROWS;
            g_count = 0;                     // reset for next (graph) launch
        }
    }
}

extern "C" void kernel_launch(void* const* d_in, const int* in_sizes, int n_in,
                              void* d_out, int out_size)
{
    const float* E   = (const float*)d_in[0];
    const int*   lab = (const int*)d_in[1];
    float*       out = (float*)d_out;

    cudaFuncSetAttribute(npair_mma, cudaFuncAttributeMaxDynamicSharedMemorySize, SM_TOTAL);

    stage<<<256, 256>>>(E, lab);
    npair_mma<<<GRID, NTHREADS, SM_TOTAL>>>(out);
}

// round 15
// speedup vs baseline: 23.7818x; 1.4411x over previous
#include <cuda_runtime.h>
#include <cuda_fp16.h>
#include <cstdint>
#include <math.h>

#define N_ROWS   8192
#define K_DIM    128
#define MT       128
#define NT       128
#define NTHREADS 256              // 8 warps
#define GRID     296              // 2 CTAs per SM
#define RBLOCKS  64
#define CTILES   64
#define TRI_TOTAL 2080            // upper-triangle tiles (incl. diagonal)
#define LOG2E    1.4426950408889634f
#define SCALE_H  1.2011224087864498f   // sqrt(log2e): GEMM yields sim*log2e
#define M_L2     (0.1f * LOG2E)

// ---- static device scratch ----
__device__ __align__(16) __half g_Eh[N_ROWS * K_DIM];  // fp16(E * sqrt(log2e))
__device__ float        g_row[N_ROWS];                 // atomically accumulated row sums
__device__ int          g_lab[N_ROWS];
__device__ unsigned int g_count = 0;

// ---- smem byte offsets (fp16 tiles, 272B padded rows) ----
#define ROW_BYTES  272
#define TILE_BYTES (MT * ROW_BYTES)              // 34816
#define SM_A       0
#define SM_B       TILE_BYTES                    // 2 buffers
#define SM_LAB     (SM_B + 2 * TILE_BYTES)       // int[2][128]   (1024 B)
#define SM_COL     (SM_LAB + 1024)               // float[4][128] (2048 B)
#define SM_RED     (SM_COL + 2048)               // float[256]    (1024 B)
#define SM_TOTAL   (SM_RED + 1024)               // 108544 B -> 2 CTAs/SM

__device__ __forceinline__ uint32_t smem_u32(const void* p) {
    uint32_t a;
    asm("{ .reg .u64 t; cvta.to.shared.u64 t, %1; cvt.u32.u64 %0, t; }" : "=r"(a) : "l"(p));
    return a;
}
__device__ __forceinline__ void cp_async16(uint32_t dst, const void* src) {
    asm volatile("cp.async.cg.shared.global [%0], [%1], 16;" :: "r"(dst), "l"(src) : "memory");
}
#define CP_COMMIT() asm volatile("cp.async.commit_group;" ::: "memory")
#define CP_WAIT0()  asm volatile("cp.async.wait_group 0;" ::: "memory")

__device__ __forceinline__ void ldsm4(uint32_t& r0, uint32_t& r1, uint32_t& r2, uint32_t& r3,
                                      uint32_t addr) {
    asm volatile("ldmatrix.sync.aligned.m8n8.x4.shared.b16 {%0,%1,%2,%3}, [%4];"
                 : "=r"(r0), "=r"(r1), "=r"(r2), "=r"(r3) : "r"(addr));
}
__device__ __forceinline__ void ldsm2(uint32_t& r0, uint32_t& r1, uint32_t addr) {
    asm volatile("ldmatrix.sync.aligned.m8n8.x2.shared.b16 {%0,%1}, [%2];"
                 : "=r"(r0), "=r"(r1) : "r"(addr));
}
__device__ __forceinline__ void mma_f16(float& c0, float& c1, float& c2, float& c3,
                                        uint32_t a0, uint32_t a1, uint32_t a2, uint32_t a3,
                                        uint32_t b0, uint32_t b1) {
    asm volatile(
        "mma.sync.aligned.m16n8k16.row.col.f32.f16.f16.f32 "
        "{%0,%1,%2,%3}, {%4,%5,%6,%7}, {%8,%9}, {%0,%1,%2,%3};"
        : "+f"(c0), "+f"(c1), "+f"(c2), "+f"(c3)
        : "r"(a0), "r"(a1), "r"(a2), "r"(a3), "r"(b0), "r"(b1));
}
__device__ __forceinline__ float ex2(float x) {
    float r;
    asm("ex2.approx.f32 %0, %1;" : "=f"(r) : "f"(x));
    return r;
}

// ---------------------------------------------------------------------------
// Stage: fp16-convert scaled embeddings, zero row sums, fix labels.
// Labels: reference asks int64 but JAX w/o x64 emits int32 -> auto-detect.
// ---------------------------------------------------------------------------
__global__ void stage(const float* __restrict__ E, const int* __restrict__ lab32)
{
    const float4* E4 = (const float4*)E;
    int t = blockIdx.x * blockDim.x + threadIdx.x;   // 0..65535
    #pragma unroll
    for (int i = 0; i < 4; i++) {
        int idx = i * 65536 + t;                     // 262144 float4 total
        float4 v = E4[idx];
        __half2 h0 = __floats2half2_rn(v.x * SCALE_H, v.y * SCALE_H);
        __half2 h1 = __floats2half2_rn(v.z * SCALE_H, v.w * SCALE_H);
        uint2 u;
        u.x = *(const uint32_t*)&h0;
        u.y = *(const uint32_t*)&h1;
        reinterpret_cast<uint2*>(g_Eh)[idx] = u;
    }
    if (t < N_ROWS) g_row[t] = 0.f;
    if (blockIdx.x == 0) {
        int local = 0;
        for (int i = threadIdx.x; i < N_ROWS / 2; i += blockDim.x)
            local |= lab32[2 * i + 1];
        int any_odd = __syncthreads_or(local);
        if (any_odd) {
            for (int i = threadIdx.x; i < N_ROWS; i += blockDim.x) g_lab[i] = lab32[i];
        } else {
            for (int i = threadIdx.x; i < N_ROWS; i += blockDim.x) g_lab[i] = lab32[2 * i];
        }
    }
}

// ---------------------------------------------------------------------------
// Main: upper-triangle tiles only (symmetry: each off-diag value feeds both
// its row and its column sum). 296 CTAs x 8 warps, warp tile 32x64, A in
// registers, 2-deep B pipeline, ex2 epilogue with pre-exponent sign flip.
// ---------------------------------------------------------------------------
__global__ __launch_bounds__(NTHREADS, 2)
void npair_mma(float* __restrict__ out)
{
    extern __shared__ char smem[];
    const uint32_t sbase = smem_u32(smem);
    int*   labS = (int*)(smem + SM_LAB);      // [2][NT]
    float* colS = (float*)(smem + SM_COL);    // [4][128] per-wm col partials

    const int tid = threadIdx.x;
    const int wid = tid >> 5, lid = tid & 31;
    const int wm = wid >> 1;                  // 0..3 row 32-block
    const int wn = wid & 1;                   // 0..1 col 64-block
    const int qr = lid >> 2;                  // accum frag row 0..7
    const int qc = lid & 3;                   // accum frag colpair 0..3
    const int lq = lid >> 3;                  // ldmatrix quadrant 0..3
    const int lr = lid & 7;                   // ldmatrix row 0..7

    const int cta   = blockIdx.x;
    const int start = (int)(((long long)cta * TRI_TOTAL) / GRID);
    const int end   = (int)(((long long)(cta + 1) * TRI_TOTAL) / GRID);

    const uint32_t aBase = sbase + SM_A +
        (uint32_t)(wm * 32 + (lq & 1) * 8 + lr) * ROW_BYTES + (uint32_t)(lq >> 1) * 16;
    const uint32_t bBase0 = (uint32_t)(wn * 64 + lr) * ROW_BYTES +
                            (uint32_t)((lid >> 3) & 1) * 16;

    // locate (rb, ct) for flattened triangle index 'start' (row-major, ct>=rb)
    int rb = 0, acc0 = 0;
    while (acc0 + (CTILES - rb) <= start) { acc0 += (CTILES - rb); rb++; }
    int ct = rb + (start - acc0);
    int rbn = rb, ctn = ct;                   // coords of t+1
    { if (++ctn == CTILES) { rbn++; ctn = rbn; } }

    // zero col partial slabs (A-load barriers below order this vs epilogue)
    if (tid < 128) {
        colS[tid] = 0.f; colS[128 + tid] = 0.f; colS[256 + tid] = 0.f; colS[384 + tid] = 0.f;
    }

    // ---- prefetch first B tile + labels ----
    {
        uint32_t bdst = sbase + SM_B + (start & 1) * TILE_BYTES;
        #pragma unroll
        for (int u = 0; u < 8; u++) {
            int idx = u * NTHREADS + tid;
            int row = idx >> 4, c = idx & 15;
            cp_async16(bdst + row * ROW_BYTES + c * 16,
                       g_Eh + (size_t)(ct * NT + row) * K_DIM + c * 8);
        }
        CP_COMMIT();
        if (tid < NT) labS[(start & 1) * NT + tid] = g_lab[ct * NT + tid];
    }

    uint32_t afr[8][2][4];
    int labr[4];
    float rowsum[4] = {0.f, 0.f, 0.f, 0.f};
    int cur_rb = -1;

    for (int t = start; t < end; t++) {
        const int buf = t & 1;
        const bool isDiag = (ct == rb);

        if (rb != cur_rb) {
            if (cur_rb >= 0) {   // flush row partials of previous rowblock
                #pragma unroll
                for (int i = 0; i < 4; i++) {
                    rowsum[i] += __shfl_xor_sync(0xFFFFFFFF, rowsum[i], 1);
                    rowsum[i] += __shfl_xor_sync(0xFFFFFFFF, rowsum[i], 2);
                }
                if (qc == 0) {
                    #pragma unroll
                    for (int i = 0; i < 4; i++)
                        atomicAdd(&g_row[cur_rb * MT + wm * 32 + i * 8 + qr], rowsum[i]);
                }
                #pragma unroll
                for (int i = 0; i < 4; i++) rowsum[i] = 0.f;
            }
            __syncthreads();
            #pragma unroll
            for (int u = 0; u < 8; u++) {        // load A tile
                int idx = u * NTHREADS + tid;
                int row = idx >> 4, c = idx & 15;
                uint4 v = *reinterpret_cast<const uint4*>(
                    (const char*)g_Eh + ((size_t)(rb * MT + row) * K_DIM + c * 8) * 2);
                *reinterpret_cast<uint4*>(smem + SM_A + row * ROW_BYTES + c * 16) = v;
            }
            __syncthreads();
            #pragma unroll
            for (int ks = 0; ks < 8; ks++)
                #pragma unroll
                for (int rt = 0; rt < 2; rt++)
                    ldsm4(afr[ks][rt][0], afr[ks][rt][1], afr[ks][rt][2], afr[ks][rt][3],
                          aBase + rt * 16 * ROW_BYTES + ks * 32);
            #pragma unroll
            for (int i = 0; i < 4; i++)
                labr[i] = g_lab[rb * MT + wm * 32 + i * 8 + qr];
            cur_rb = rb;
        }

        CP_WAIT0();
        __syncthreads();   // tile t ready; prev tile's readers + col flush done

        if (t + 1 < end) {                       // prefetch next tile
            uint32_t bdst = sbase + SM_B + ((t + 1) & 1) * TILE_BYTES;
            #pragma unroll
            for (int u = 0; u < 8; u++) {
                int idx = u * NTHREADS + tid;
                int row = idx >> 4, c = idx & 15;
                cp_async16(bdst + row * ROW_BYTES + c * 16,
                           g_Eh + (size_t)(ctn * NT + row) * K_DIM + c * 8);
            }
            CP_COMMIT();
            if (tid < NT) labS[((t + 1) & 1) * NT + tid] = g_lab[ctn * NT + tid];
        }

        // ---- tile (rb, ct): 8 chunks of 8 columns ----
        const uint32_t bB = sbase + SM_B + buf * TILE_BYTES + bBase0;
        const int labBase = buf * NT + wn * 64 + 2 * qc;

        #pragma unroll
        for (int c = 0; c < 8; c++) {
            float acc[8];
            #pragma unroll
            for (int q = 0; q < 8; q++) acc[q] = 0.f;
            #pragma unroll
            for (int ks = 0; ks < 8; ks++) {
                uint32_t b0, b1;
                ldsm2(b0, b1, bB + c * 8 * ROW_BYTES + ks * 32);
                mma_f16(acc[0], acc[1], acc[2], acc[3],
                        afr[ks][0][0], afr[ks][0][1], afr[ks][0][2], afr[ks][0][3],
                        b0, b1);
                mma_f16(acc[4], acc[5], acc[6], acc[7],
                        afr[ks][1][0], afr[ks][1][1], afr[ks][1][2], afr[ks][1][3],
                        b0, b1);
            }
            const int lc0 = labS[labBase + c * 8];
            const int lc1 = labS[labBase + c * 8 + 1];
            float cs0 = 0.f, cs1 = 0.f;
            #pragma unroll
            for (int rt = 0; rt < 2; rt++) {
                float u0 = acc[rt * 4 + 0] - M_L2;
                float u1 = acc[rt * 4 + 1] - M_L2;
                float u2 = acc[rt * 4 + 2] - M_L2;
                float u3 = acc[rt * 4 + 3] - M_L2;
                uint32_t f0 = (labr[rt * 2 + 0] == lc0) ? 0x80000000u : 0u;
                uint32_t f1 = (labr[rt * 2 + 0] == lc1) ? 0x80000000u : 0u;
                uint32_t f2 = (labr[rt * 2 + 1] == lc0) ? 0x80000000u : 0u;
                uint32_t f3 = (labr[rt * 2 + 1] == lc1) ? 0x80000000u : 0u;
                float e0 = ex2(__uint_as_float(__float_as_uint(u0) ^ f0));
                float e1 = ex2(__uint_as_float(__float_as_uint(u1) ^ f1));
                float e2 = ex2(__uint_as_float(__float_as_uint(u2) ^ f2));
                float e3 = ex2(__uint_as_float(__float_as_uint(u3) ^ f3));
                rowsum[rt * 2 + 0] += e0 + e1;
                rowsum[rt * 2 + 1] += e2 + e3;
                cs0 += e0 + e2;
                cs1 += e1 + e3;
            }
            if (!isDiag) {       // column partials (off-diag tiles only)
                cs0 += __shfl_xor_sync(0xFFFFFFFF, cs0, 4);
                cs0 += __shfl_xor_sync(0xFFFFFFFF, cs0, 8);
                cs0 += __shfl_xor_sync(0xFFFFFFFF, cs0, 16);
                cs1 += __shfl_xor_sync(0xFFFFFFFF, cs1, 4);
                cs1 += __shfl_xor_sync(0xFFFFFFFF, cs1, 8);
                cs1 += __shfl_xor_sync(0xFFFFFFFF, cs1, 16);
                if (lid < 4) {
                    int ci = wm * 128 + wn * 64 + c * 8 + 2 * qc;
                    colS[ci]     += cs0;
                    colS[ci + 1] += cs1;
                }
            }
        }

        __syncthreads();   // all col partials of this tile written
        if (!isDiag && tid < 128) {
            float s = colS[tid] + colS[128 + tid] + colS[256 + tid] + colS[384 + tid];
            atomicAdd(&g_row[ct * NT + tid], s);
            colS[tid] = 0.f; colS[128 + tid] = 0.f; colS[256 + tid] = 0.f; colS[384 + tid] = 0.f;
        }

        rb = rbn; ct = ctn;
        if (++ctn == CTILES) { rbn++; ctn = rbn; }
    }

    // ---- flush last rowblock's row partials ----
    #pragma unroll
    for (int i = 0; i < 4; i++) {
        rowsum[i] += __shfl_xor_sync(0xFFFFFFFF, rowsum[i], 1);
        rowsum[i] += __shfl_xor_sync(0xFFFFFFFF, rowsum[i], 2);
    }
    if (qc == 0) {
        #pragma unroll
        for (int i = 0; i < 4; i++)
            atomicAdd(&g_row[cur_rb * MT + wm * 32 + i * 8 + qr], rowsum[i]);
    }

    // ---- fused final reduction: last-arriving CTA computes the loss ----
    __shared__ int lastFlag;
    if (tid == 0) {
        __threadfence();
        unsigned int old = atomicAdd(&g_count, 1u);
        lastFlag = (old == (unsigned)(gridDim.x - 1));
    }
    __syncthreads();
    if (lastFlag) {
        __threadfence();
        float s = 0.f;
        #pragma unroll
        for (int i = 0; i < N_ROWS / NTHREADS; i++) {
            int r = i * NTHREADS + tid;      // fixed order per thread
            s += logf(g_row[r]);
        }
        float* redf = (float*)(smem + SM_RED);
        redf[tid] = s;
        __syncthreads();
        for (int st = NTHREADS / 2; st > 0; st >>= 1) {
            if (tid < st) redf[tid] += redf[tid + st];
            __syncthreads();
        }
        if (tid == 0) {
            out[0] = redf[0] / (float)N_ROWS;
            g_count = 0;                     // reset for next (graph) launch
        }
    }
}

extern "C" void kernel_launch(void* const* d_in, const int* in_sizes, int n_in,
                              void* d_out, int out_size)
{
    const float* E   = (const float*)d_in[0];
    const int*   lab = (const int*)d_in[1];
    float*       out = (float*)d_out;

    cudaFuncSetAttribute(npair_mma, cudaFuncAttributeMaxDynamicSharedMemorySize, SM_TOTAL);

    stage<<<256, 256>>>(E, lab);
    npair_mma<<<GRID, NTHREADS, SM_TOTAL>>>(out);
}

// round 17
// speedup vs baseline: 24.6503x; 1.0365x over previous
#include <cuda_runtime.h>
#include <cuda_fp16.h>
#include <cstdint>
#include <math.h>

#define N_ROWS   8192
#define K_DIM    128
#define MT       128
#define NT       128
#define NTHREADS 256              // 8 warps
#define GRID     296              // 2 CTAs per SM
#define CTILES   64
#define TRI_TOTAL 2080            // upper-triangle tiles (incl. diagonal)
#define PAIR_LEN 65               // tiles in pair (p, 63-p)
#define LOG2E    1.4426950408889634f
#define SCALE_H  1.2011224087864498f   // sqrt(log2e): GEMM yields sim*log2e
#define M_L2     (0.1f * LOG2E)

// ---- static device scratch ----
__device__ __align__(16) __half g_Eh[N_ROWS * K_DIM];  // fp16(E * sqrt(log2e))
__device__ float        g_row[N_ROWS];                 // atomically accumulated row sums
__device__ int          g_lab[N_ROWS];
__device__ unsigned int g_count = 0;

// ---- smem byte offsets (fp16 tiles, 272B padded rows) ----
#define ROW_BYTES  272
#define TILE_BYTES (MT * ROW_BYTES)              // 34816
#define SM_A       0
#define SM_B       TILE_BYTES                    // 2 buffers
#define SM_LAB     (SM_B + 2 * TILE_BYTES)       // int[2][128]   (1024 B)
#define SM_COL     (SM_LAB + 1024)               // float[4][128] (2048 B)
#define SM_RED     (SM_COL + 2048)               // float[256]    (1024 B)
#define SM_TOTAL   (SM_RED + 1024)               // 108544 B -> 2 CTAs/SM

__device__ __forceinline__ uint32_t smem_u32(const void* p) {
    uint32_t a;
    asm("{ .reg .u64 t; cvta.to.shared.u64 t, %1; cvt.u32.u64 %0, t; }" : "=r"(a) : "l"(p));
    return a;
}
__device__ __forceinline__ void cp_async16(uint32_t dst, const void* src) {
    asm volatile("cp.async.cg.shared.global [%0], [%1], 16;" :: "r"(dst), "l"(src) : "memory");
}
#define CP_COMMIT() asm volatile("cp.async.commit_group;" ::: "memory")
#define CP_WAIT0()  asm volatile("cp.async.wait_group 0;" ::: "memory")

__device__ __forceinline__ void ldsm4(uint32_t& r0, uint32_t& r1, uint32_t& r2, uint32_t& r3,
                                      uint32_t addr) {
    asm volatile("ldmatrix.sync.aligned.m8n8.x4.shared.b16 {%0,%1,%2,%3}, [%4];"
                 : "=r"(r0), "=r"(r1), "=r"(r2), "=r"(r3) : "r"(addr));
}
__device__ __forceinline__ void ldsm2(uint32_t& r0, uint32_t& r1, uint32_t addr) {
    asm volatile("ldmatrix.sync.aligned.m8n8.x2.shared.b16 {%0,%1}, [%2];"
                 : "=r"(r0), "=r"(r1) : "r"(addr));
}
__device__ __forceinline__ void mma_f16(float& c0, float& c1, float& c2, float& c3,
                                        uint32_t a0, uint32_t a1, uint32_t a2, uint32_t a3,
                                        uint32_t b0, uint32_t b1) {
    asm volatile(
        "mma.sync.aligned.m16n8k16.row.col.f32.f16.f16.f32 "
        "{%0,%1,%2,%3}, {%4,%5,%6,%7}, {%8,%9}, {%0,%1,%2,%3};"
        : "+f"(c0), "+f"(c1), "+f"(c2), "+f"(c3)
        : "r"(a0), "r"(a1), "r"(a2), "r"(a3), "r"(b0), "r"(b1));
}
__device__ __forceinline__ float ex2(float x) {
    float r;
    asm("ex2.approx.f32 %0, %1;" : "=f"(r) : "f"(x));
    return r;
}
// pair-balanced triangle coords from flattened index f = p*65 + l
__device__ __forceinline__ void triCoords(int p, int l, int& rb, int& ct) {
    if (l < 64 - p) { rb = p;      ct = p + l; }
    else            { rb = 63 - p; ct = l - 1; }
}

// ---------------------------------------------------------------------------
// Stage: fp16-convert scaled embeddings, zero row sums, fix labels.
// Labels: reference asks int64 but JAX w/o x64 emits int32 -> auto-detect.
// ---------------------------------------------------------------------------
__global__ void stage(const float* __restrict__ E, const int* __restrict__ lab32)
{
    const float4* E4 = (const float4*)E;
    int t = blockIdx.x * blockDim.x + threadIdx.x;   // 0..65535
    #pragma unroll
    for (int i = 0; i < 4; i++) {
        int idx = i * 65536 + t;                     // 262144 float4 total
        float4 v = E4[idx];
        __half2 h0 = __floats2half2_rn(v.x * SCALE_H, v.y * SCALE_H);
        __half2 h1 = __floats2half2_rn(v.z * SCALE_H, v.w * SCALE_H);
        uint2 u;
        u.x = *(const uint32_t*)&h0;
        u.y = *(const uint32_t*)&h1;
        reinterpret_cast<uint2*>(g_Eh)[idx] = u;
    }
    if (t < N_ROWS) g_row[t] = 0.f;
    if (blockIdx.x == 0) {
        int local = 0;
        for (int i = threadIdx.x; i < N_ROWS / 2; i += blockDim.x)
            local |= lab32[2 * i + 1];
        int any_odd = __syncthreads_or(local);
        if (any_odd) {
            for (int i = threadIdx.x; i < N_ROWS; i += blockDim.x) g_lab[i] = lab32[i];
        } else {
            for (int i = threadIdx.x; i < N_ROWS; i += blockDim.x) g_lab[i] = lab32[2 * i];
        }
    }
}

// ---------------------------------------------------------------------------
// Main: pair-balanced upper-triangle schedule (rowblock p paired with 63-p:
// 65 tiles per pair -> <=2 rowblock switches per CTA). Warp tile 32x64; two
// 8-col chunks interleaved in the ks loop (4 independent HMMA chains); bias
// folded into accumulator init; ex2 epilogue feeds row + column sums.
// ---------------------------------------------------------------------------
__global__ __launch_bounds__(NTHREADS, 2)
void npair_mma(float* __restrict__ out)
{
    extern __shared__ char smem[];
    const uint32_t sbase = smem_u32(smem);
    int*   labS = (int*)(smem + SM_LAB);      // [2][NT]
    float* colS = (float*)(smem + SM_COL);    // [4][128] per-wm col partials

    const int tid = threadIdx.x;
    const int wid = tid >> 5, lid = tid & 31;
    const int wm = wid >> 1;                  // 0..3 row 32-block
    const int wn = wid & 1;                   // 0..1 col 64-block
    const int qr = lid >> 2;                  // accum frag row 0..7
    const int qc = lid & 3;                   // accum frag colpair 0..3
    const int lq = lid >> 3;                  // ldmatrix quadrant 0..3
    const int lr = lid & 7;                   // ldmatrix row 0..7

    const int cta   = blockIdx.x;
    const int start = (int)(((long long)cta * TRI_TOTAL) / GRID);
    const int end   = (int)(((long long)(cta + 1) * TRI_TOTAL) / GRID);

    const uint32_t aBase = sbase + SM_A +
        (uint32_t)(wm * 32 + (lq & 1) * 8 + lr) * ROW_BYTES + (uint32_t)(lq >> 1) * 16;
    const uint32_t bBase0 = (uint32_t)(wn * 64 + lr) * ROW_BYTES +
                            (uint32_t)((lid >> 3) & 1) * 16;

    int p = start / PAIR_LEN, l = start % PAIR_LEN;
    int rb, ct;
    triCoords(p, l, rb, ct);

    // zero col partial slabs
    if (tid < 128) {
        colS[tid] = 0.f; colS[128 + tid] = 0.f; colS[256 + tid] = 0.f; colS[384 + tid] = 0.f;
    }

    // ---- prefetch first B tile + labels ----
    {
        uint32_t bdst = sbase + SM_B + (start & 1) * TILE_BYTES;
        #pragma unroll
        for (int u = 0; u < 8; u++) {
            int idx = u * NTHREADS + tid;
            int row = idx >> 4, c = idx & 15;
            cp_async16(bdst + row * ROW_BYTES + c * 16,
                       g_Eh + (size_t)(ct * NT + row) * K_DIM + c * 8);
        }
        CP_COMMIT();
        if (tid < NT) labS[(start & 1) * NT + tid] = g_lab[ct * NT + tid];
    }

    uint32_t afr[8][2][4];
    int labr[4];
    float rowsum[4] = {0.f, 0.f, 0.f, 0.f};
    int cur_rb = -1;

    for (int t = start; t < end; t++) {
        const int buf = t & 1;
        const bool isDiag = (ct == rb);

        // coords of t+1 (for prefetch + advance)
        int pn = p, ln = l + 1;
        if (ln == PAIR_LEN) { ln = 0; pn++; }
        int rbn, ctn;
        triCoords(pn, ln, rbn, ctn);

        if (rb != cur_rb) {
            if (cur_rb >= 0) {   // flush row partials of previous rowblock
                #pragma unroll
                for (int i = 0; i < 4; i++) {
                    rowsum[i] += __shfl_xor_sync(0xFFFFFFFF, rowsum[i], 1);
                    rowsum[i] += __shfl_xor_sync(0xFFFFFFFF, rowsum[i], 2);
                }
                if (qc == 0) {
                    #pragma unroll
                    for (int i = 0; i < 4; i++)
                        atomicAdd(&g_row[cur_rb * MT + wm * 32 + i * 8 + qr], rowsum[i]);
                }
                #pragma unroll
                for (int i = 0; i < 4; i++) rowsum[i] = 0.f;
            }
            __syncthreads();
            #pragma unroll
            for (int u = 0; u < 8; u++) {        // load A tile
                int idx = u * NTHREADS + tid;
                int row = idx >> 4, c = idx & 15;
                uint4 v = *reinterpret_cast<const uint4*>(
                    (const char*)g_Eh + ((size_t)(rb * MT + row) * K_DIM + c * 8) * 2);
                *reinterpret_cast<uint4*>(smem + SM_A + row * ROW_BYTES + c * 16) = v;
            }
            __syncthreads();
            #pragma unroll
            for (int ks = 0; ks < 8; ks++)
                #pragma unroll
                for (int rt = 0; rt < 2; rt++)
                    ldsm4(afr[ks][rt][0], afr[ks][rt][1], afr[ks][rt][2], afr[ks][rt][3],
                          aBase + rt * 16 * ROW_BYTES + ks * 32);
            #pragma unroll
            for (int i = 0; i < 4; i++)
                labr[i] = g_lab[rb * MT + wm * 32 + i * 8 + qr];
            cur_rb = rb;
        }

        CP_WAIT0();
        __syncthreads();   // tile t ready; prev tile's readers + col flush done

        if (t + 1 < end) {                       // prefetch next tile
            uint32_t bdst = sbase + SM_B + ((t + 1) & 1) * TILE_BYTES;
            #pragma unroll
            for (int u = 0; u < 8; u++) {
                int idx = u * NTHREADS + tid;
                int row = idx >> 4, c = idx & 15;
                cp_async16(bdst + row * ROW_BYTES + c * 16,
                           g_Eh + (size_t)(ctn * NT + row) * K_DIM + c * 8);
            }
            CP_COMMIT();
            if (tid < NT) labS[((t + 1) & 1) * NT + tid] = g_lab[ctn * NT + tid];
        }

        // ---- tile (rb, ct): 4 pairs of interleaved 8-col chunks ----
        const uint32_t bB = sbase + SM_B + buf * TILE_BYTES + bBase0;
        const int labBase = buf * NT + wn * 64 + 2 * qc;

        #pragma unroll
        for (int cp2 = 0; cp2 < 4; cp2++) {
            const int c0 = 2 * cp2, c1 = 2 * cp2 + 1;
            float acc[2][2][4];                  // [chunk][rt][q], bias folded in
            #pragma unroll
            for (int h = 0; h < 2; h++)
                #pragma unroll
                for (int rt = 0; rt < 2; rt++)
                    #pragma unroll
                    for (int q = 0; q < 4; q++) acc[h][rt][q] = -M_L2;

            #pragma unroll
            for (int ks = 0; ks < 8; ks++) {
                uint32_t b0, b1, b2, b3;
                ldsm2(b0, b1, bB + c0 * 8 * ROW_BYTES + ks * 32);
                ldsm2(b2, b3, bB + c1 * 8 * ROW_BYTES + ks * 32);
                mma_f16(acc[0][0][0], acc[0][0][1], acc[0][0][2], acc[0][0][3],
                        afr[ks][0][0], afr[ks][0][1], afr[ks][0][2], afr[ks][0][3], b0, b1);
                mma_f16(acc[0][1][0], acc[0][1][1], acc[0][1][2], acc[0][1][3],
                        afr[ks][1][0], afr[ks][1][1], afr[ks][1][2], afr[ks][1][3], b0, b1);
                mma_f16(acc[1][0][0], acc[1][0][1], acc[1][0][2], acc[1][0][3],
                        afr[ks][0][0], afr[ks][0][1], afr[ks][0][2], afr[ks][0][3], b2, b3);
                mma_f16(acc[1][1][0], acc[1][1][1], acc[1][1][2], acc[1][1][3],
                        afr[ks][1][0], afr[ks][1][1], afr[ks][1][2], afr[ks][1][3], b2, b3);
            }

            #pragma unroll
            for (int h = 0; h < 2; h++) {
                const int c = 2 * cp2 + h;
                const int lc0 = labS[labBase + c * 8];
                const int lc1 = labS[labBase + c * 8 + 1];
                float cs0 = 0.f, cs1 = 0.f;
                #pragma unroll
                for (int rt = 0; rt < 2; rt++) {
                    float u0 = acc[h][rt][0];
                    float u1 = acc[h][rt][1];
                    float u2 = acc[h][rt][2];
                    float u3 = acc[h][rt][3];
                    uint32_t f0 = (labr[rt * 2 + 0] == lc0) ? 0x80000000u : 0u;
                    uint32_t f1 = (labr[rt * 2 + 0] == lc1) ? 0x80000000u : 0u;
                    uint32_t f2 = (labr[rt * 2 + 1] == lc0) ? 0x80000000u : 0u;
                    uint32_t f3 = (labr[rt * 2 + 1] == lc1) ? 0x80000000u : 0u;
                    float e0 = ex2(__uint_as_float(__float_as_uint(u0) ^ f0));
                    float e1 = ex2(__uint_as_float(__float_as_uint(u1) ^ f1));
                    float e2 = ex2(__uint_as_float(__float_as_uint(u2) ^ f2));
                    float e3 = ex2(__uint_as_float(__float_as_uint(u3) ^ f3));
                    rowsum[rt * 2 + 0] += e0 + e1;
                    rowsum[rt * 2 + 1] += e2 + e3;
                    cs0 += e0 + e2;
                    cs1 += e1 + e3;
                }
                if (!isDiag) {       // column partials (off-diag tiles only)
                    cs0 += __shfl_xor_sync(0xFFFFFFFF, cs0, 4);
                    cs0 += __shfl_xor_sync(0xFFFFFFFF, cs0, 8);
                    cs0 += __shfl_xor_sync(0xFFFFFFFF, cs0, 16);
                    cs1 += __shfl_xor_sync(0xFFFFFFFF, cs1, 4);
                    cs1 += __shfl_xor_sync(0xFFFFFFFF, cs1, 8);
                    cs1 += __shfl_xor_sync(0xFFFFFFFF, cs1, 16);
                    if (lid < 4) {
                        int ci = wm * 128 + wn * 64 + c * 8 + 2 * qc;
                        colS[ci]     += cs0;
                        colS[ci + 1] += cs1;
                    }
                }
            }
        }

        __syncthreads();   // all col partials of this tile written
        if (!isDiag && tid < 128) {
            float s = colS[tid] + colS[128 + tid] + colS[256 + tid] + colS[384 + tid];
            atomicAdd(&g_row[ct * NT + tid], s);
            colS[tid] = 0.f; colS[128 + tid] = 0.f; colS[256 + tid] = 0.f; colS[384 + tid] = 0.f;
        }

        p = pn; l = ln; rb = rbn; ct = ctn;
    }

    // ---- flush last rowblock's row partials ----
    #pragma unroll
    for (int i = 0; i < 4; i++) {
        rowsum[i] += __shfl_xor_sync(0xFFFFFFFF, rowsum[i], 1);
        rowsum[i] += __shfl_xor_sync(0xFFFFFFFF, rowsum[i], 2);
    }
    if (qc == 0) {
        #pragma unroll
        for (int i = 0; i < 4; i++)
            atomicAdd(&g_row[cur_rb * MT + wm * 32 + i * 8 + qr], rowsum[i]);
    }

    // ---- fused final reduction: last-arriving CTA computes the loss ----
    __shared__ int lastFlag;
    if (tid == 0) {
        __threadfence();
        unsigned int old = atomicAdd(&g_count, 1u);
        lastFlag = (old == (unsigned)(gridDim.x - 1));
    }
    __syncthreads();
    if (lastFlag) {
        __threadfence();
        float s = 0.f;
        #pragma unroll
        for (int i = 0; i < N_ROWS / NTHREADS; i++) {
            int r = i * NTHREADS + tid;      // fixed order per thread
            s += logf(g_row[r]);
        }
        float* redf = (float*)(smem + SM_RED);
        redf[tid] = s;
        __syncthreads();
        for (int st = NTHREADS / 2; st > 0; st >>= 1) {
            if (tid < st) redf[tid] += redf[tid + st];
            __syncthreads();
        }
        if (tid == 0) {
            out[0] = redf[0] / (float)N_ROWS;
            g_count = 0;                     // reset for next (graph) launch
        }
    }
}

extern "C" void kernel_launch(void* const* d_in, const int* in_sizes, int n_in,
                              void* d_out, int out_size)
{
    const float* E   = (const float*)d_in[0];
    const int*   lab = (const int*)d_in[1];
    float*       out = (float*)d_out;

    cudaFuncSetAttribute(npair_mma, cudaFuncAttributeMaxDynamicSharedMemorySize, SM_TOTAL);

    stage<<<256, 256>>>(E, lab);
    npair_mma<<<GRID, NTHREADS, SM_TOTAL>>>(out);
}